// round 7
// baseline (speedup 1.0000x reference)
#include <cuda_runtime.h>
#include <cuda_bf16.h>

#define SEQ   512
#define BATCH 128
#define DIN   512
#define DH    1024
#define DOUT  256
#define WROW  (DIN + DH)   // 1536, W_i2h row length

#define NBLK   128
#define NTHR   256
#define KSPLIT 8
#define KSL    128          // k-slice depth (1024/8)
#define JT     64           // j-tile width (1024/16)

// SMEM layout for persistent kernel (floats)
#define SWH_FLOATS (KSL * JT)        // Wh slice [128 k][64 j] = 8192
#define SH_STRIDE  132               // padded row (128 k + pad)
#define SH_FLOATS  (BATCH * SH_STRIDE)
#define SMEM_BYTES ((SWH_FLOATS + SH_FLOATS) * 4)   // 100352 B

// Device-global scratch (allocation-free rule: __device__ arrays)
__device__ float    g_xW[SEQ * BATCH * DH];          // precomputed input projections
__device__ float    g_H[BATCH * DH];                 // current hidden state
__device__ float    g_Cpart[KSPLIT * BATCH * DH];    // split-K partials
__device__ unsigned g_bar_count;
__device__ unsigned g_bar_flag;

// ---------------- packed fp32x2 helpers (sm_100+) ----------------
__device__ __forceinline__ unsigned long long pack2(float x, float y) {
    unsigned long long r;
    asm("mov.b64 %0, {%1, %2};" : "=l"(r) : "f"(x), "f"(y));
    return r;
}
__device__ __forceinline__ unsigned long long fma2(unsigned long long a,
                                                   unsigned long long b,
                                                   unsigned long long c) {
    unsigned long long d;
    asm("fma.rn.f32x2 %0, %1, %2, %3;" : "=l"(d) : "l"(a), "l"(b), "l"(c));
    return d;
}
__device__ __forceinline__ float2 unpack2(unsigned long long v) {
    float2 r;
    asm("mov.b64 {%0, %1}, %2;" : "=f"(r.x), "=f"(r.y) : "l"(v));
    return r;
}

// ---------------------------------------------------------------------------
// Init: copy initial hidden state, reset barrier (fresh state every launch)
// ---------------------------------------------------------------------------
__global__ void k_init(const float* __restrict__ hidden)
{
    int i = blockIdx.x * blockDim.x + threadIdx.x;
    if (i < BATCH * DH) g_H[i] = hidden[i];
    if (i == 0) { g_bar_count = 0; g_bar_flag = 0; }
}

// ---------------------------------------------------------------------------
// Precompute xW[s,b,:] = x[s,b,:] @ Wx   (M=65536, N=1024, K=512)
// fp32 SGEMM: 128x128 block tile, 8x8 microtile (f32x2-packed), BK=8,
// double-buffered SMEM.
// ---------------------------------------------------------------------------
__global__ void __launch_bounds__(256, 2) k_xw(
    const float* __restrict__ A,     // x, [65536][512]
    const float* __restrict__ W)     // W_i2h, [1024][1536]; Wx[k][n] = W[n][k]
{
    __shared__ float sA[2][8][132];
    __shared__ float sB[2][8][132];

    const int tid = threadIdx.x;
    const int m0  = blockIdx.y << 7;
    const int n0  = blockIdx.x << 7;
    const int row = tid >> 1;        // 0..127
    const int q   = tid & 1;         // which float4 of the 8-wide k chunk
    const int tm  = tid & 15;
    const int tn  = tid >> 4;

    const float* Aptr = A + (m0 + row) * DIN  + (q << 2);
    const float* Wptr = W + (n0 + row) * WROW + (q << 2);

    // load tile 0
    {
        float4 a = *(const float4*)Aptr;
        float4 b = *(const float4*)Wptr;
        sA[0][q * 4 + 0][row] = a.x; sA[0][q * 4 + 1][row] = a.y;
        sA[0][q * 4 + 2][row] = a.z; sA[0][q * 4 + 3][row] = a.w;
        sB[0][q * 4 + 0][row] = b.x; sB[0][q * 4 + 1][row] = b.y;
        sB[0][q * 4 + 2][row] = b.z; sB[0][q * 4 + 3][row] = b.w;
    }
    __syncthreads();

    unsigned long long acc2[8][4];
    #pragma unroll
    for (int i = 0; i < 8; ++i)
        #pragma unroll
        for (int j = 0; j < 4; ++j) acc2[i][j] = 0ull;   // two packed 0.0f

    int buf = 0;
    for (int cb = 0; cb < 64; ++cb) {
        float4 ra, rb;
        const bool more = (cb < 63);
        if (more) {
            ra = *(const float4*)(Aptr + (cb + 1) * 8);
            rb = *(const float4*)(Wptr + (cb + 1) * 8);
        }
        #pragma unroll
        for (int k = 0; k < 8; ++k) {
            float4 a0 = *(const float4*)&sA[buf][k][tm << 2];
            float4 a1 = *(const float4*)&sA[buf][k][64 + (tm << 2)];
            float4 b0 = *(const float4*)&sB[buf][k][tn << 2];
            float4 b1 = *(const float4*)&sB[buf][k][64 + (tn << 2)];
            unsigned long long bp[4] = {
                pack2(b0.x, b0.y), pack2(b0.z, b0.w),
                pack2(b1.x, b1.y), pack2(b1.z, b1.w)
            };
            float am[8] = {a0.x, a0.y, a0.z, a0.w, a1.x, a1.y, a1.z, a1.w};
            #pragma unroll
            for (int i = 0; i < 8; ++i) {
                unsigned long long ad = pack2(am[i], am[i]);
                #pragma unroll
                for (int p = 0; p < 4; ++p)
                    acc2[i][p] = fma2(ad, bp[p], acc2[i][p]);
            }
        }
        if (more) {
            int nb = buf ^ 1;
            sA[nb][q * 4 + 0][row] = ra.x; sA[nb][q * 4 + 1][row] = ra.y;
            sA[nb][q * 4 + 2][row] = ra.z; sA[nb][q * 4 + 3][row] = ra.w;
            sB[nb][q * 4 + 0][row] = rb.x; sB[nb][q * 4 + 1][row] = rb.y;
            sB[nb][q * 4 + 2][row] = rb.z; sB[nb][q * 4 + 3][row] = rb.w;
            __syncthreads();
            buf = nb;
        }
    }

    #pragma unroll
    for (int i = 0; i < 8; ++i) {
        int m = m0 + ((i < 4) ? ((tm << 2) + i) : (64 + (tm << 2) + (i - 4)));
        float2 p0 = unpack2(acc2[i][0]);
        float2 p1 = unpack2(acc2[i][1]);
        float2 p2 = unpack2(acc2[i][2]);
        float2 p3 = unpack2(acc2[i][3]);
        float4 v0 = make_float4(p0.x, p0.y, p1.x, p1.y);
        float4 v1 = make_float4(p2.x, p2.y, p3.x, p3.y);
        *(float4*)&g_xW[m * DH + n0 + (tn << 2)]      = v0;
        *(float4*)&g_xW[m * DH + n0 + 64 + (tn << 2)] = v1;
    }
}

// ---------------------------------------------------------------------------
// Grid barrier: generation counter, reset by k_init each launch.
// ---------------------------------------------------------------------------
__device__ __forceinline__ void grid_barrier(unsigned nblk, unsigned& gen)
{
    __threadfence();
    __syncthreads();
    if (threadIdx.x == 0) {
        gen += 1;
        unsigned a = atomicAdd(&g_bar_count, 1u);
        if (a == nblk - 1u) {
            atomicExch(&g_bar_count, 0u);
            __threadfence();
            *(volatile unsigned*)&g_bar_flag = gen;
        } else {
            while (*(volatile unsigned*)&g_bar_flag != gen) { }
        }
    }
    __syncthreads();
}

// ---------------------------------------------------------------------------
// Persistent recurrence kernel. 128 blocks (co-resident).
// Block decode: jx (16 j-tiles of 64) x kx (8 k-slices of 128).
// Wh slice [128k][64j] stays in SMEM for the whole kernel.
// Phase 1: microtile 4b x 8j per thread, f32x2-packed FMA.
// Phase 2: reduce 8 split-K partials + xW + bias, tanh.
// ---------------------------------------------------------------------------
__global__ void __launch_bounds__(NTHR, 1) k_rnn(
    const float* __restrict__ Wi2h, const float* __restrict__ bi2h,
    const float* __restrict__ Wh2o, const float* __restrict__ bh2o,
    float* __restrict__ out, int out_size)
{
    extern __shared__ float smem[];
    float* sWh = smem;               // [128 k][64 j]
    float* sH  = smem + SWH_FLOATS;  // [128 b][132] (padded)

    const int tid = threadIdx.x;
    const int blk = blockIdx.x;
    const int jx  = blk & 15;        // j-tile
    const int kx  = blk >> 4;        // k-slice
    const int j0  = jx * JT;
    const int k0  = kx * KSL;

    // Load Wh slice (transposed to [k][j]) ONCE. Wh[k][j] = W_i2h[j][DIN+k].
    for (int p = tid; p < JT * (KSL / 4); p += NTHR) {
        int j  = p >> 5;             // 0..63
        int kq = p & 31;             // float4 index along k
        float4 v = *(const float4*)&Wi2h[(j0 + j) * WROW + DIN + k0 + (kq << 2)];
        sWh[(kq * 4 + 0) * JT + j] = v.x;
        sWh[(kq * 4 + 1) * JT + j] = v.y;
        sWh[(kq * 4 + 2) * JT + j] = v.z;
        sWh[(kq * 4 + 3) * JT + j] = v.w;
    }

    const int jt = tid & 7;          // j-oct (8 octs x 8 = 64 j)
    const int bt = tid >> 3;         // b-quad (32 quads x 4 = 128 b)
    unsigned gen = 0;
    const int gtid = blk * NTHR + tid;                // 0..32767
    const float4* Cp4 = (const float4*)g_Cpart;
    const float4* xW4 = (const float4*)g_xW;
    float4* H4 = (float4*)g_H;
    const int pj = (gtid << 2) & (DH - 1);
    const float4 bias = *(const float4*)&bi2h[pj];

    const float* wp = sWh + (jt << 3);
    const float* hp = sH + (bt << 2) * SH_STRIDE;

    for (int t = 0; t < SEQ; ++t) {
        // Load H slice [128 b][128 k] into SMEM
        for (int p = tid; p < BATCH * (KSL / 4); p += NTHR) {
            int bl = p >> 5;
            int kq = p & 31;
            float4 v = *(const float4*)&g_H[bl * DH + k0 + (kq << 2)];
            *(float4*)&sH[bl * SH_STRIDE + (kq << 2)] = v;
        }
        __syncthreads();

        // Phase 1: partial GEMM, microtile 4b x 8j over 128 k, f32x2 packed
        unsigned long long acc2[4][4];
        #pragma unroll
        for (int i = 0; i < 4; ++i)
            #pragma unroll
            for (int p = 0; p < 4; ++p) acc2[i][p] = 0ull;

        #pragma unroll 4
        for (int k = 0; k < KSL; ++k) {
            float4 w0 = *(const float4*)(wp + k * JT);
            float4 w1 = *(const float4*)(wp + k * JT + 4);
            unsigned long long wpk[4] = {
                pack2(w0.x, w0.y), pack2(w0.z, w0.w),
                pack2(w1.x, w1.y), pack2(w1.z, w1.w)
            };
            #pragma unroll
            for (int i = 0; i < 4; ++i) {
                float h = hp[i * SH_STRIDE + k];
                unsigned long long hd = pack2(h, h);
                #pragma unroll
                for (int p = 0; p < 4; ++p)
                    acc2[i][p] = fma2(hd, wpk[p], acc2[i][p]);
            }
        }

        #pragma unroll
        for (int i = 0; i < 4; ++i) {
            float2 p0 = unpack2(acc2[i][0]);
            float2 p1 = unpack2(acc2[i][1]);
            float2 p2 = unpack2(acc2[i][2]);
            float2 p3 = unpack2(acc2[i][3]);
            float4 v0 = make_float4(p0.x, p0.y, p1.x, p1.y);
            float4 v1 = make_float4(p2.x, p2.y, p3.x, p3.y);
            float* dst = &g_Cpart[kx * (BATCH * DH) +
                                  ((bt << 2) + i) * DH + j0 + (jt << 3)];
            *(float4*)dst       = v0;
            *(float4*)(dst + 4) = v1;
        }

        grid_barrier(gridDim.x, gen);

        // Phase 2: reduce 8 partials + xW + bias, tanh, write H (1 float4/thread)
        {
            float4 s = Cp4[gtid];
            #pragma unroll
            for (int sp = 1; sp < KSPLIT; ++sp) {
                float4 c = Cp4[sp * 32768 + gtid];
                s.x += c.x; s.y += c.y; s.z += c.z; s.w += c.w;
            }
            float4 xw = xW4[t * 32768 + gtid];
            float4 r;
            r.x = tanhf(s.x + xw.x + bias.x);
            r.y = tanhf(s.y + xw.y + bias.y);
            r.z = tanhf(s.z + xw.z + bias.z);
            r.w = tanhf(s.w + xw.w + bias.w);
            H4[gtid] = r;
        }

        grid_barrier(gridDim.x, gen);
    }

    // ------------------- Epilogue: logits + softmax -------------------
    // One block per batch row (NBLK == BATCH). Thread = output class.
    {
        float* sv   = smem;          // h row [1024]
        float* sred = smem + 1024;   // reduction [256]
        const int b = blk;

        ((float4*)sv)[tid] = *(const float4*)&g_H[b * DH + (tid << 2)];
        __syncthreads();

        float acc = 0.f;
        const float4* wr = (const float4*)(Wh2o + tid * DH);
        #pragma unroll 8
        for (int qq = 0; qq < DH / 4; ++qq) {
            float4 w = wr[qq];
            float4 h = ((const float4*)sv)[qq];
            acc += w.x * h.x + w.y * h.y + w.z * h.z + w.w * h.w;
        }
        float logit = acc + bh2o[tid];

        sred[tid] = logit;
        __syncthreads();
        for (int s = 128; s > 0; s >>= 1) {
            if (tid < s) sred[tid] = fmaxf(sred[tid], sred[tid + s]);
            __syncthreads();
        }
        float mx = sred[0];
        __syncthreads();
        float e = expf(logit - mx);
        sred[tid] = e;
        __syncthreads();
        for (int s = 128; s > 0; s >>= 1) {
            if (tid < s) sred[tid] += sred[tid + s];
            __syncthreads();
        }
        float inv = 1.f / sred[0];
        out[b * DOUT + tid] = e * inv;
    }

    // h_final (second output tensor), grid-stride copy
    if (out_size >= BATCH * DOUT + BATCH * DH) {
        for (int i = gtid; i < BATCH * DH; i += NBLK * NTHR)
            out[BATCH * DOUT + i] = g_H[i];
    }
}

// ---------------------------------------------------------------------------
extern "C" void kernel_launch(void* const* d_in, const int* in_sizes, int n_in,
                              void* d_out, int out_size)
{
    const float* x      = (const float*)d_in[0];
    const float* hidden = (const float*)d_in[1];
    const float* Wi2h   = (const float*)d_in[2];
    const float* bi2h   = (const float*)d_in[3];
    const float* Wh2o   = (const float*)d_in[4];
    const float* bh2o   = (const float*)d_in[5];
    float* out = (float*)d_out;

    cudaFuncSetAttribute(k_rnn, cudaFuncAttributeMaxDynamicSharedMemorySize,
                         SMEM_BYTES);

    k_init<<<512, 256>>>(hidden);

    dim3 gx(DH / 128, (SEQ * BATCH) / 128);   // (8, 512)
    k_xw<<<gx, 256>>>(x, Wi2h);

    k_rnn<<<NBLK, NTHR, SMEM_BYTES>>>(Wi2h, bi2h, Wh2o, bh2o, out, out_size);
}

// round 11
// speedup vs baseline: 1.1993x; 1.1993x over previous
#include <cuda_runtime.h>
#include <cuda_bf16.h>
#include <cstdint>

#define SEQ   512
#define BATCH 128
#define DIN   512
#define DH    1024
#define DOUT  256
#define WROW  (DIN + DH)   // 1536

#define NBLK   128
#define NTHR   256
#define KSPLIT 8
#define KSL    128          // k-slice depth (1024/8)
#define JT     64           // j-tile width (1024/16)

// ---- SMEM layout for k_rnn (bytes) ----
// sWfrag: prebuilt B fragments: 16 kc x 8 nt x 32 lanes x float4 = 64 KB
// sH2:    H hi/lo interleaved, k-permuted: 128 rows x 136 float2 = 136 KB
#define SWF_OFF   0
#define SWF_BYTES 65536
#define SH2_OFF   65536
#define S2        136                       // sH2 row stride in float2 units
#define SH2_BYTES (BATCH * S2 * 8)          // 139264
#define SMEM_RNN  (SWF_BYTES + SH2_BYTES)   // 204800 B

// Device-global scratch
__device__ float    g_xW[SEQ * BATCH * DH];
__device__ float    g_H[BATCH * DH];
__device__ float    g_Cpart[KSPLIT * BATCH * DH];
__device__ unsigned g_bar_count;
__device__ unsigned g_bar_flag;

// ---------------- helpers ----------------
__device__ __forceinline__ float to_tf32(float x) {
    float r;
    asm("cvt.rna.tf32.f32 %0, %1;" : "=f"(r) : "f"(x));
    return r;
}
// mma.sync m16n8k8 tf32 (baseline PTX, valid on .target sm_103).
// PTX-documented fragment layout (g = lane>>2, t = lane&3):
//   A: a0=A[g][t]  a1=A[g+8][t]  a2=A[g][t+4]  a3=A[g+8][t+4]
//   B: b0=B[t][n=g]  b1=B[t+4][n=g]
//   D: c0=D[g][2t] c1=D[g][2t+1] c2=D[g+8][2t] c3=D[g+8][2t+1]
__device__ __forceinline__ void mma8(float* d,
                                     uint32_t a0, uint32_t a1, uint32_t a2, uint32_t a3,
                                     uint32_t b0, uint32_t b1) {
    asm volatile(
        "mma.sync.aligned.m16n8k8.row.col.f32.tf32.tf32.f32 "
        "{%0,%1,%2,%3}, {%4,%5,%6,%7}, {%8,%9}, {%0,%1,%2,%3};"
        : "+f"(d[0]), "+f"(d[1]), "+f"(d[2]), "+f"(d[3])
        : "r"(a0), "r"(a1), "r"(a2), "r"(a3), "r"(b0), "r"(b1));
}

// ---------------------------------------------------------------------------
__global__ void k_init(const float* __restrict__ hidden)
{
    int i = blockIdx.x * blockDim.x + threadIdx.x;
    if (i < BATCH * DH) g_H[i] = hidden[i];
    if (i == 0) { g_bar_count = 0; g_bar_flag = 0; }
}

// ---------------------------------------------------------------------------
// xW = x @ Wx  (fp32 SGEMM, 128x128 tile, 8x8 microtile, BK=8, double buffer)
// — unchanged proven R5 version.
// ---------------------------------------------------------------------------
__global__ void __launch_bounds__(256, 2) k_xw(
    const float* __restrict__ A, const float* __restrict__ W)
{
    __shared__ float sA[2][8][132];
    __shared__ float sB[2][8][132];

    const int tid = threadIdx.x;
    const int m0  = blockIdx.y << 7;
    const int n0  = blockIdx.x << 7;
    const int row = tid >> 1;
    const int q   = tid & 1;
    const int tm  = tid & 15;
    const int tn  = tid >> 4;

    const float* Aptr = A + (m0 + row) * DIN  + (q << 2);
    const float* Wptr = W + (n0 + row) * WROW + (q << 2);

    {
        float4 a = *(const float4*)Aptr;
        float4 b = *(const float4*)Wptr;
        sA[0][q*4+0][row]=a.x; sA[0][q*4+1][row]=a.y; sA[0][q*4+2][row]=a.z; sA[0][q*4+3][row]=a.w;
        sB[0][q*4+0][row]=b.x; sB[0][q*4+1][row]=b.y; sB[0][q*4+2][row]=b.z; sB[0][q*4+3][row]=b.w;
    }
    __syncthreads();

    float acc[8][8];
    #pragma unroll
    for (int i = 0; i < 8; ++i)
        #pragma unroll
        for (int j = 0; j < 8; ++j) acc[i][j] = 0.f;

    int buf = 0;
    for (int cb = 0; cb < 64; ++cb) {
        float4 ra, rb;
        const bool more = (cb < 63);
        if (more) {
            ra = *(const float4*)(Aptr + (cb + 1) * 8);
            rb = *(const float4*)(Wptr + (cb + 1) * 8);
        }
        #pragma unroll
        for (int k = 0; k < 8; ++k) {
            float4 a0 = *(const float4*)&sA[buf][k][tm << 2];
            float4 a1 = *(const float4*)&sA[buf][k][64 + (tm << 2)];
            float4 b0 = *(const float4*)&sB[buf][k][tn << 2];
            float4 b1 = *(const float4*)&sB[buf][k][64 + (tn << 2)];
            float am[8] = {a0.x,a0.y,a0.z,a0.w,a1.x,a1.y,a1.z,a1.w};
            float bn[8] = {b0.x,b0.y,b0.z,b0.w,b1.x,b1.y,b1.z,b1.w};
            #pragma unroll
            for (int i = 0; i < 8; ++i)
                #pragma unroll
                for (int j = 0; j < 8; ++j)
                    acc[i][j] += am[i] * bn[j];
        }
        if (more) {
            int nb = buf ^ 1;
            sA[nb][q*4+0][row]=ra.x; sA[nb][q*4+1][row]=ra.y; sA[nb][q*4+2][row]=ra.z; sA[nb][q*4+3][row]=ra.w;
            sB[nb][q*4+0][row]=rb.x; sB[nb][q*4+1][row]=rb.y; sB[nb][q*4+2][row]=rb.z; sB[nb][q*4+3][row]=rb.w;
            __syncthreads();
            buf = nb;
        }
    }

    #pragma unroll
    for (int i = 0; i < 8; ++i) {
        int m = m0 + ((i < 4) ? ((tm << 2) + i) : (64 + (tm << 2) + (i - 4)));
        float4 v0 = make_float4(acc[i][0], acc[i][1], acc[i][2], acc[i][3]);
        float4 v1 = make_float4(acc[i][4], acc[i][5], acc[i][6], acc[i][7]);
        *(float4*)&g_xW[m * DH + n0 + (tn << 2)]      = v0;
        *(float4*)&g_xW[m * DH + n0 + 64 + (tn << 2)] = v1;
    }
}

// ---------------------------------------------------------------------------
__device__ __forceinline__ void grid_barrier(unsigned nblk, unsigned& gen)
{
    __threadfence();
    __syncthreads();
    if (threadIdx.x == 0) {
        gen += 1;
        unsigned a = atomicAdd(&g_bar_count, 1u);
        if (a == nblk - 1u) {
            atomicExch(&g_bar_count, 0u);
            __threadfence();
            *(volatile unsigned*)&g_bar_flag = gen;
        } else {
            while (*(volatile unsigned*)&g_bar_flag != gen) { }
        }
    }
    __syncthreads();
}

// ---------------------------------------------------------------------------
// Persistent recurrence. Phase 1 = mma.sync m16n8k8 tf32, fused 3xTF32
// (Ah*Bh + Al*Bh + Ah*Bl) in one fp32 accumulator. Corrected tf32 fragments.
// 128 blocks: jx (16 j-tiles of 64) x kx (8 k-slices of 128).
// Warp w handles batch rows [16w, 16w+16), all 64 j (8 n-tiles).
// ---------------------------------------------------------------------------
__global__ void __launch_bounds__(NTHR, 1) k_rnn(
    const float* __restrict__ Wi2h, const float* __restrict__ bi2h,
    const float* __restrict__ Wh2o, const float* __restrict__ bh2o,
    float* __restrict__ out, int out_size)
{
    extern __shared__ char smem[];
    const float4* sWf = (const float4*)(smem + SWF_OFF);
    float2*       sH2 = (float2*)(smem + SH2_OFF);

    const int tid  = threadIdx.x;
    const int blk  = blockIdx.x;
    const int jx   = blk & 15;
    const int kx   = blk >> 4;
    const int j0   = jx * JT;
    const int k0   = kx * KSL;
    const int wrp  = tid >> 5;
    const int lane = tid & 31;
    const int g    = lane >> 2;      // group id
    const int tq   = lane & 3;       // thread-in-group
    const int brow = (wrp << 4) + g; // A rows brow, brow+8

    // ---- Build B fragments (Wh hi/lo, tf32 m16n8k8 layout) ONCE ----
    // b0 = B[k=tq][n=g], b1 = B[k=tq+4][n=g]; B[k][j] = W_i2h[j][DIN+k].
    // Stored per (kc, nt, lane) as float4 (bh0, bh1, bl0, bl1).
    for (int p = tid; p < 16 * 8 * 32; p += NTHR) {
        int kc = p >> 8;
        int nt = (p >> 5) & 7;
        int ln = p & 31;
        int k  = k0 + kc * 8 + (ln & 3);      // b0 k-row
        int j  = j0 + nt * 8 + (ln >> 2);     // n col
        float w0 = Wi2h[j * WROW + DIN + k];
        float w1 = Wi2h[j * WROW + DIN + k + 4];
        float h0 = to_tf32(w0), l0 = to_tf32(w0 - h0);
        float h1 = to_tf32(w1), l1 = to_tf32(w1 - h1);
        ((float4*)(smem + SWF_OFF))[p] = make_float4(h0, h1, l0, l1);
    }

    unsigned gen = 0;
    const int gtid = blk * NTHR + tid;
    const float4* Cp4 = (const float4*)g_Cpart;
    const float4* xW4 = (const float4*)g_xW;
    float4* H4 = (float4*)g_H;
    const int pj = (gtid << 2) & (DH - 1);
    const float4 bias = *(const float4*)&bi2h[pj];

    float* part_row0 = &g_Cpart[kx * (BATCH * DH) + brow * DH + j0 + (tq << 1)];

    for (int t = 0; t < SEQ; ++t) {
        // ---- split H slice [128 b][128 k] -> hi/lo float2, k-permuted ----
        // Within each 8-k chunk, element k stored at pos (k&3)*2 + (k>>2)
        // so (k=t, k=t+4) pairs are contiguous -> one LDS.128 per A row frag.
        for (int p = tid; p < BATCH * (KSL / 4); p += NTHR) {
            int r   = p >> 5;
            int q4  = p & 31;                 // float4 index (4 consecutive k)
            float4 v = *(const float4*)&g_H[r * DH + k0 + (q4 << 2)];
            int chunk = q4 >> 1;              // k-chunk 0..15
            int base  = q4 & 1;               // 0: k0-3 -> pos 0,2,4,6 ; 1: k4-7 -> 1,3,5,7
            float2* dst = &sH2[r * S2 + (chunk << 3) + base];
            float h, l;
            h = to_tf32(v.x); l = to_tf32(v.x - h); dst[0] = make_float2(h, l);
            h = to_tf32(v.y); l = to_tf32(v.y - h); dst[2] = make_float2(h, l);
            h = to_tf32(v.z); l = to_tf32(v.z - h); dst[4] = make_float2(h, l);
            h = to_tf32(v.w); l = to_tf32(v.w - h); dst[6] = make_float2(h, l);
        }
        __syncthreads();

        // ---- Phase 1: tf32 MMA, 16 k-chunks x 8 n-tiles x 3 passes ----
        float acc[8][4];
        #pragma unroll
        for (int nt = 0; nt < 8; ++nt)
            #pragma unroll
            for (int c = 0; c < 4; ++c) acc[nt][c] = 0.f;

        #pragma unroll 2
        for (int kc = 0; kc < 16; ++kc) {
            // A0 = (hi(k=tq), lo(k=tq), hi(k=tq+4), lo(k=tq+4)) for row brow
            float4 A0 = *(const float4*)&sH2[brow * S2 + (kc << 3) + (tq << 1)];
            float4 A1 = *(const float4*)&sH2[(brow + 8) * S2 + (kc << 3) + (tq << 1)];
            // fragment regs: a0=A[g][t] a1=A[g+8][t] a2=A[g][t+4] a3=A[g+8][t+4]
            uint32_t ah0 = __float_as_uint(A0.x), al0 = __float_as_uint(A0.y);
            uint32_t ah2 = __float_as_uint(A0.z), al2 = __float_as_uint(A0.w);
            uint32_t ah1 = __float_as_uint(A1.x), al1 = __float_as_uint(A1.y);
            uint32_t ah3 = __float_as_uint(A1.z), al3 = __float_as_uint(A1.w);
            #pragma unroll
            for (int nt = 0; nt < 8; ++nt) {
                float4 bf = sWf[((kc << 3) + nt) * 32 + lane];
                uint32_t bh0 = __float_as_uint(bf.x), bh1 = __float_as_uint(bf.y);
                uint32_t bl0 = __float_as_uint(bf.z), bl1 = __float_as_uint(bf.w);
                mma8(acc[nt], ah0, ah1, ah2, ah3, bh0, bh1);  // Ah*Bh
                mma8(acc[nt], al0, al1, al2, al3, bh0, bh1);  // Al*Bh
                mma8(acc[nt], ah0, ah1, ah2, ah3, bl0, bl1);  // Ah*Bl
            }
        }

        // ---- store split-K partials (documented C layout) ----
        #pragma unroll
        for (int nt = 0; nt < 8; ++nt) {
            *(float2*)(part_row0 + nt * 8)          = make_float2(acc[nt][0], acc[nt][1]);
            *(float2*)(part_row0 + 8 * DH + nt * 8) = make_float2(acc[nt][2], acc[nt][3]);
        }

        grid_barrier(gridDim.x, gen);

        // ---- Phase 2: reduce 8 partials + xW + bias, tanh -> g_H ----
        {
            float4 s = Cp4[gtid];
            #pragma unroll
            for (int sp = 1; sp < KSPLIT; ++sp) {
                float4 c = Cp4[sp * 32768 + gtid];
                s.x += c.x; s.y += c.y; s.z += c.z; s.w += c.w;
            }
            float4 xw = xW4[t * 32768 + gtid];
            float4 r;
            r.x = tanhf(s.x + xw.x + bias.x);
            r.y = tanhf(s.y + xw.y + bias.y);
            r.z = tanhf(s.z + xw.z + bias.z);
            r.w = tanhf(s.w + xw.w + bias.w);
            H4[gtid] = r;
        }

        grid_barrier(gridDim.x, gen);
    }

    // ------------------- Epilogue: logits + softmax -------------------
    {
        float* sv   = (float*)smem;          // h row [1024]
        float* sred = (float*)smem + 1024;   // reduction [256]
        const int b = blk;

        ((float4*)sv)[tid] = *(const float4*)&g_H[b * DH + (tid << 2)];
        __syncthreads();

        float acc = 0.f;
        const float4* wr = (const float4*)(Wh2o + tid * DH);
        #pragma unroll 8
        for (int qq = 0; qq < DH / 4; ++qq) {
            float4 w = wr[qq];
            float4 h = ((const float4*)sv)[qq];
            acc += w.x * h.x + w.y * h.y + w.z * h.z + w.w * h.w;
        }
        float logit = acc + bh2o[tid];

        sred[tid] = logit;
        __syncthreads();
        for (int s = 128; s > 0; s >>= 1) {
            if (tid < s) sred[tid] = fmaxf(sred[tid], sred[tid + s]);
            __syncthreads();
        }
        float mx = sred[0];
        __syncthreads();
        float e = expf(logit - mx);
        sred[tid] = e;
        __syncthreads();
        for (int s = 128; s > 0; s >>= 1) {
            if (tid < s) sred[tid] += sred[tid + s];
            __syncthreads();
        }
        float inv = 1.f / sred[0];
        out[b * DOUT + tid] = e * inv;
    }

    // h_final (second output tensor)
    if (out_size >= BATCH * DOUT + BATCH * DH) {
        for (int i = gtid; i < BATCH * DH; i += NBLK * NTHR)
            out[BATCH * DOUT + i] = g_H[i];
    }
}

// ---------------------------------------------------------------------------
extern "C" void kernel_launch(void* const* d_in, const int* in_sizes, int n_in,
                              void* d_out, int out_size)
{
    const float* x      = (const float*)d_in[0];
    const float* hidden = (const float*)d_in[1];
    const float* Wi2h   = (const float*)d_in[2];
    const float* bi2h   = (const float*)d_in[3];
    const float* Wh2o   = (const float*)d_in[4];
    const float* bh2o   = (const float*)d_in[5];
    float* out = (float*)d_out;

    cudaFuncSetAttribute(k_rnn, cudaFuncAttributeMaxDynamicSharedMemorySize,
                         SMEM_RNN);

    k_init<<<512, 256>>>(hidden);

    dim3 gx(DH / 128, (SEQ * BATCH) / 128);   // (8, 512)
    k_xw<<<gx, 256>>>(x, Wi2h);

    k_rnn<<<NBLK, NTHR, SMEM_RNN>>>(Wi2h, bi2h, Wh2o, bh2o, out, out_size);
}

// round 12
// speedup vs baseline: 1.6568x; 1.3815x over previous
#include <cuda_runtime.h>
#include <cuda_bf16.h>
#include <cstdint>

#define SEQ   512
#define BATCH 128
#define DIN   512
#define DH    1024
#define DOUT  256
#define WROW  (DIN + DH)   // 1536

#define NBLK   128
#define NTHR   256
#define KSPLIT 8
#define KSL    128          // k-slice depth (1024/8)
#define JT     64           // j-tile width (1024/16)

// ---- SMEM layout for k_rnn (bytes) ----
// sWf: B fragments: 8 kc x 8 nt x 32 lanes x uint4(b0h,b1h,b0l,b1l) = 32 KB
// sH : H hi/lo bf16, fragment-ordered: 128 rows x 576 B (512 data + 64 pad)
#define SWF_OFF    0
#define SWF_BYTES  32768
#define SH_OFF     32768
#define SH_STRIDE  576
#define SMEM_RNN   (SWF_BYTES + BATCH * SH_STRIDE)   // 106496 B

// Device-global scratch
__device__ float    g_xW[SEQ * BATCH * DH];
__device__ float    g_H[BATCH * DH];          // fp32 H (final step only)
__device__ uint32_t g_H2[BATCH * 1024];       // hi/lo bf16 pairs, frag-ordered
__device__ float    g_Cpart[KSPLIT * BATCH * DH];
__device__ unsigned g_bar_count;
__device__ unsigned g_bar_flag;

// ---------------- helpers ----------------
__device__ __forceinline__ uint32_t bf16pair(float lo_elem, float hi_elem) {
    __nv_bfloat162 p = __floats2bfloat162_rn(lo_elem, hi_elem); // .x=lo (low half)
    return *(uint32_t*)&p;
}
__device__ __forceinline__ float bf16of(float x) {
    return __bfloat162float(__float2bfloat16(x));
}
// mma.sync m16n8k16 bf16 (baseline PTX sm_80+, valid on .target sm_103).
// A: a0={A[g][2t],A[g][2t+1]} a1={A[g+8][2t..]} a2={A[g][2t+8..]} a3={A[g+8][2t+8..]}
// B: b0={B[2t][g],B[2t+1][g]} b1={B[2t+8][g],B[2t+9][g]}
// D: c0=D[g][2t] c1=D[g][2t+1] c2=D[g+8][2t] c3=D[g+8][2t+1]
__device__ __forceinline__ void mma16(float* d,
                                      uint32_t a0, uint32_t a1, uint32_t a2, uint32_t a3,
                                      uint32_t b0, uint32_t b1) {
    asm volatile(
        "mma.sync.aligned.m16n8k16.row.col.f32.bf16.bf16.f32 "
        "{%0,%1,%2,%3}, {%4,%5,%6,%7}, {%8,%9}, {%0,%1,%2,%3};"
        : "+f"(d[0]), "+f"(d[1]), "+f"(d[2]), "+f"(d[3])
        : "r"(a0), "r"(a1), "r"(a2), "r"(a3), "r"(b0), "r"(b1));
}

// ---------------------------------------------------------------------------
// Init: g_H fp32, g_H2 hi/lo split (fragment-ordered), barrier reset.
// g_H2 slot for (row b, col k): u32 index b*1024 + (k>>4)*16 + ((k&7)>>1)*4
//                               + ((k>>3)&1)*2, +1 for lo; parity k&1 in half.
// ---------------------------------------------------------------------------
__global__ void k_init(const float* __restrict__ hidden)
{
    int i = blockIdx.x * blockDim.x + threadIdx.x;
    if (i < BATCH * DH) g_H[i] = hidden[i];
    if (i < BATCH * DH / 2) {
        int b = i >> 9;
        int k = (i & 511) << 1;                  // even k of the pair
        float x0 = hidden[b * DH + k];
        float x1 = hidden[b * DH + k + 1];
        float h0 = bf16of(x0), h1 = bf16of(x1);
        int o = (k >> 4) * 16 + (((k & 7) >> 1) << 2) + (((k >> 3) & 1) << 1);
        g_H2[b * 1024 + o]     = bf16pair(h0, h1);
        g_H2[b * 1024 + o + 1] = bf16pair(x0 - h0, x1 - h1);
    }
    if (i == 0) { g_bar_count = 0; g_bar_flag = 0; }
}

// ---------------------------------------------------------------------------
// xW = x @ Wx  (fp32 SGEMM, unchanged proven R5 version)
// ---------------------------------------------------------------------------
__global__ void __launch_bounds__(256, 2) k_xw(
    const float* __restrict__ A, const float* __restrict__ W)
{
    __shared__ float sA[2][8][132];
    __shared__ float sB[2][8][132];

    const int tid = threadIdx.x;
    const int m0  = blockIdx.y << 7;
    const int n0  = blockIdx.x << 7;
    const int row = tid >> 1;
    const int q   = tid & 1;
    const int tm  = tid & 15;
    const int tn  = tid >> 4;

    const float* Aptr = A + (m0 + row) * DIN  + (q << 2);
    const float* Wptr = W + (n0 + row) * WROW + (q << 2);

    {
        float4 a = *(const float4*)Aptr;
        float4 b = *(const float4*)Wptr;
        sA[0][q*4+0][row]=a.x; sA[0][q*4+1][row]=a.y; sA[0][q*4+2][row]=a.z; sA[0][q*4+3][row]=a.w;
        sB[0][q*4+0][row]=b.x; sB[0][q*4+1][row]=b.y; sB[0][q*4+2][row]=b.z; sB[0][q*4+3][row]=b.w;
    }
    __syncthreads();

    float acc[8][8];
    #pragma unroll
    for (int i = 0; i < 8; ++i)
        #pragma unroll
        for (int j = 0; j < 8; ++j) acc[i][j] = 0.f;

    int buf = 0;
    for (int cb = 0; cb < 64; ++cb) {
        float4 ra, rb;
        const bool more = (cb < 63);
        if (more) {
            ra = *(const float4*)(Aptr + (cb + 1) * 8);
            rb = *(const float4*)(Wptr + (cb + 1) * 8);
        }
        #pragma unroll
        for (int k = 0; k < 8; ++k) {
            float4 a0 = *(const float4*)&sA[buf][k][tm << 2];
            float4 a1 = *(const float4*)&sA[buf][k][64 + (tm << 2)];
            float4 b0 = *(const float4*)&sB[buf][k][tn << 2];
            float4 b1 = *(const float4*)&sB[buf][k][64 + (tn << 2)];
            float am[8] = {a0.x,a0.y,a0.z,a0.w,a1.x,a1.y,a1.z,a1.w};
            float bn[8] = {b0.x,b0.y,b0.z,b0.w,b1.x,b1.y,b1.z,b1.w};
            #pragma unroll
            for (int i = 0; i < 8; ++i)
                #pragma unroll
                for (int j = 0; j < 8; ++j)
                    acc[i][j] += am[i] * bn[j];
        }
        if (more) {
            int nb = buf ^ 1;
            sA[nb][q*4+0][row]=ra.x; sA[nb][q*4+1][row]=ra.y; sA[nb][q*4+2][row]=ra.z; sA[nb][q*4+3][row]=ra.w;
            sB[nb][q*4+0][row]=rb.x; sB[nb][q*4+1][row]=rb.y; sB[nb][q*4+2][row]=rb.z; sB[nb][q*4+3][row]=rb.w;
            __syncthreads();
            buf = nb;
        }
    }

    #pragma unroll
    for (int i = 0; i < 8; ++i) {
        int m = m0 + ((i < 4) ? ((tm << 2) + i) : (64 + (tm << 2) + (i - 4)));
        float4 v0 = make_float4(acc[i][0], acc[i][1], acc[i][2], acc[i][3]);
        float4 v1 = make_float4(acc[i][4], acc[i][5], acc[i][6], acc[i][7]);
        *(float4*)&g_xW[m * DH + n0 + (tn << 2)]      = v0;
        *(float4*)&g_xW[m * DH + n0 + 64 + (tn << 2)] = v1;
    }
}

// ---------------------------------------------------------------------------
__device__ __forceinline__ void grid_barrier(unsigned nblk, unsigned& gen)
{
    __threadfence();
    __syncthreads();
    if (threadIdx.x == 0) {
        gen += 1;
        unsigned a = atomicAdd(&g_bar_count, 1u);
        if (a == nblk - 1u) {
            atomicExch(&g_bar_count, 0u);
            __threadfence();
            *(volatile unsigned*)&g_bar_flag = gen;
        } else {
            while (*(volatile unsigned*)&g_bar_flag != gen) { }
        }
    }
    __syncthreads();
}

// ---------------------------------------------------------------------------
// Persistent recurrence. Phase 1 = mma.sync m16n8k16 bf16, fused bf16x3
// (Ah*Bh + Al*Bh + Ah*Bl) in fp32 accumulators. H arrives pre-split via
// cp.async copy of g_H2 (no per-step cvt work in phase 1).
// 128 blocks: jx (16 j-tiles of 64) x kx (8 k-slices of 128).
// ---------------------------------------------------------------------------
__global__ void __launch_bounds__(NTHR, 1) k_rnn(
    const float* __restrict__ Wi2h, const float* __restrict__ bi2h,
    const float* __restrict__ Wh2o, const float* __restrict__ bh2o,
    float* __restrict__ out, int out_size)
{
    extern __shared__ char smem[];
    const uint4* sWf = (const uint4*)(smem + SWF_OFF);

    const int tid  = threadIdx.x;
    const int blk  = blockIdx.x;
    const int jx   = blk & 15;
    const int kx   = blk >> 4;
    const int j0   = jx * JT;
    const int k0   = kx * KSL;
    const int wrp  = tid >> 5;
    const int lane = tid & 31;
    const int g    = lane >> 2;
    const int tq   = lane & 3;
    const int brow = (wrp << 4) + g;

    // ---- Build B fragments (Wh hi/lo bf16, m16n8k16 layout) ONCE ----
    // b0 = {B[kb+2t][n], B[kb+2t+1][n]}, b1 = {B[kb+2t+8..9][n]}, kb = kc*16.
    // B[k][j] = W_i2h[j][DIN+k]. Stored as uint4 (b0h, b1h, b0l, b1l).
    for (int p = tid; p < 8 * 8 * 32; p += NTHR) {
        int kc = p >> 8;
        int nt = (p >> 5) & 7;
        int ln = p & 31;
        int t  = ln & 3;
        int n  = j0 + nt * 8 + (ln >> 2);
        const float* wrow = &Wi2h[n * WROW + DIN + k0 + kc * 16];
        float w0 = wrow[2*t],     w1 = wrow[2*t + 1];
        float w2 = wrow[2*t + 8], w3 = wrow[2*t + 9];
        float h0 = bf16of(w0), h1 = bf16of(w1), h2 = bf16of(w2), h3 = bf16of(w3);
        uint4 frag;
        frag.x = bf16pair(h0, h1);
        frag.y = bf16pair(h2, h3);
        frag.z = bf16pair(w0 - h0, w1 - h1);
        frag.w = bf16pair(w2 - h2, w3 - h3);
        ((uint4*)(smem + SWF_OFF))[p] = frag;
    }

    unsigned gen = 0;
    const int gtid = blk * NTHR + tid;
    const float4* Cp4 = (const float4*)g_Cpart;
    const float4* xW4 = (const float4*)g_xW;
    float4* H4 = (float4*)g_H;
    const int pj = (gtid << 2) & (DH - 1);
    const float4 bias = *(const float4*)&bi2h[pj];

    float* part_row0 = &g_Cpart[kx * (BATCH * DH) + brow * DH + j0 + (tq << 1)];

    // g_H2 write slots for phase 2 (thread owns j = pj..pj+3 of row gtid>>8)
    const int rem  = pj & 15;
    const int tqA  = (rem & 7) >> 1;                 // 0 or 2
    const int half = (rem >> 3) & 1;
    uint32_t* h2row = &g_H2[(gtid >> 8) * 1024 + (pj >> 4) * 16 + tqA * 4 + half * 2];

    // cp.async source/dest for phase 1 H copy (this block's k-slice)
    const char* h2src = (const char*)g_H2 + (size_t)kx * 512;

    for (int t = 0; t < SEQ; ++t) {
        // ---- phase 1a: async copy pre-split H slice [128 rows x 512 B] ----
        for (int p = tid; p < BATCH * 32; p += NTHR) {
            int r   = p >> 5;
            int c16 = p & 31;
            uint32_t dst = (uint32_t)__cvta_generic_to_shared(
                smem + SH_OFF + r * SH_STRIDE + c16 * 16);
            const char* src = h2src + (size_t)r * 4096 + c16 * 16;
            asm volatile("cp.async.cg.shared.global [%0], [%1], 16;"
                         :: "r"(dst), "l"(src) : "memory");
        }
        asm volatile("cp.async.commit_group;" ::: "memory");
        asm volatile("cp.async.wait_group 0;" ::: "memory");
        __syncthreads();

        // ---- phase 1b: bf16x3 MMA, 8 k-chunks x 8 n-tiles x 3 passes ----
        float acc[8][4];
        #pragma unroll
        for (int nt = 0; nt < 8; ++nt)
            #pragma unroll
            for (int c = 0; c < 4; ++c) acc[nt][c] = 0.f;

        #pragma unroll 2
        for (int kc = 0; kc < 8; ++kc) {
            uint4 U0 = *(const uint4*)(smem + SH_OFF + brow * SH_STRIDE + kc * 64 + tq * 16);
            uint4 U1 = *(const uint4*)(smem + SH_OFF + (brow + 8) * SH_STRIDE + kc * 64 + tq * 16);
            // a0..a3 hi and lo
            uint32_t ah0 = U0.x, al0 = U0.y, ah2 = U0.z, al2 = U0.w;
            uint32_t ah1 = U1.x, al1 = U1.y, ah3 = U1.z, al3 = U1.w;
            #pragma unroll
            for (int nt = 0; nt < 8; ++nt) {
                uint4 bf = sWf[((kc << 3) + nt) * 32 + lane];
                mma16(acc[nt], ah0, ah1, ah2, ah3, bf.x, bf.y);  // Ah*Bh
                mma16(acc[nt], al0, al1, al2, al3, bf.x, bf.y);  // Al*Bh
                mma16(acc[nt], ah0, ah1, ah2, ah3, bf.z, bf.w);  // Ah*Bl
            }
        }

        // ---- store split-K partials (C layout: c0,c1=D[g][2t,2t+1]; c2,c3=D[g+8]) ----
        #pragma unroll
        for (int nt = 0; nt < 8; ++nt) {
            *(float2*)(part_row0 + nt * 8)          = make_float2(acc[nt][0], acc[nt][1]);
            *(float2*)(part_row0 + 8 * DH + nt * 8) = make_float2(acc[nt][2], acc[nt][3]);
        }

        grid_barrier(gridDim.x, gen);

        // ---- phase 2: reduce 8 partials + xW + bias, tanh -> g_H2 (split) ----
        {
            float4 s = Cp4[gtid];
            #pragma unroll
            for (int sp = 1; sp < KSPLIT; ++sp) {
                float4 c = Cp4[sp * 32768 + gtid];
                s.x += c.x; s.y += c.y; s.z += c.z; s.w += c.w;
            }
            float4 xw = xW4[t * 32768 + gtid];
            float4 r;
            r.x = tanhf(s.x + xw.x + bias.x);
            r.y = tanhf(s.y + xw.y + bias.y);
            r.z = tanhf(s.z + xw.z + bias.z);
            r.w = tanhf(s.w + xw.w + bias.w);

            float hx = bf16of(r.x), hy = bf16of(r.y);
            float hz = bf16of(r.z), hw = bf16of(r.w);
            h2row[0] = bf16pair(hx, hy);
            h2row[1] = bf16pair(r.x - hx, r.y - hy);
            h2row[4] = bf16pair(hz, hw);
            h2row[5] = bf16pair(r.z - hz, r.w - hw);

            if (t == SEQ - 1) H4[gtid] = r;   // fp32 H for epilogue/h_final
        }

        grid_barrier(gridDim.x, gen);
    }

    // ------------------- Epilogue: logits + softmax -------------------
    {
        float* sv   = (float*)smem;          // h row [1024]
        float* sred = (float*)smem + 1024;   // reduction [256]
        const int b = blk;

        ((float4*)sv)[tid] = *(const float4*)&g_H[b * DH + (tid << 2)];
        __syncthreads();

        float acc = 0.f;
        const float4* wr = (const float4*)(Wh2o + tid * DH);
        #pragma unroll 8
        for (int qq = 0; qq < DH / 4; ++qq) {
            float4 w = wr[qq];
            float4 h = ((const float4*)sv)[qq];
            acc += w.x * h.x + w.y * h.y + w.z * h.z + w.w * h.w;
        }
        float logit = acc + bh2o[tid];

        sred[tid] = logit;
        __syncthreads();
        for (int s = 128; s > 0; s >>= 1) {
            if (tid < s) sred[tid] = fmaxf(sred[tid], sred[tid + s]);
            __syncthreads();
        }
        float mx = sred[0];
        __syncthreads();
        float e = expf(logit - mx);
        sred[tid] = e;
        __syncthreads();
        for (int s = 128; s > 0; s >>= 1) {
            if (tid < s) sred[tid] += sred[tid + s];
            __syncthreads();
        }
        float inv = 1.f / sred[0];
        out[b * DOUT + tid] = e * inv;
    }

    // h_final (second output tensor)
    if (out_size >= BATCH * DOUT + BATCH * DH) {
        for (int i = gtid; i < BATCH * DH; i += NBLK * NTHR)
            out[BATCH * DOUT + i] = g_H[i];
    }
}

// ---------------------------------------------------------------------------
extern "C" void kernel_launch(void* const* d_in, const int* in_sizes, int n_in,
                              void* d_out, int out_size)
{
    const float* x      = (const float*)d_in[0];
    const float* hidden = (const float*)d_in[1];
    const float* Wi2h   = (const float*)d_in[2];
    const float* bi2h   = (const float*)d_in[3];
    const float* Wh2o   = (const float*)d_in[4];
    const float* bh2o   = (const float*)d_in[5];
    float* out = (float*)d_out;

    cudaFuncSetAttribute(k_rnn, cudaFuncAttributeMaxDynamicSharedMemorySize,
                         SMEM_RNN);

    k_init<<<512, 256>>>(hidden);

    dim3 gx(DH / 128, (SEQ * BATCH) / 128);   // (8, 512)
    k_xw<<<gx, 256>>>(x, Wi2h);

    k_rnn<<<NBLK, NTHR, SMEM_RNN>>>(Wi2h, bi2h, Wh2o, bh2o, out, out_size);
}

// round 13
// speedup vs baseline: 1.8703x; 1.1289x over previous
#include <cuda_runtime.h>
#include <cuda_bf16.h>
#include <cstdint>

#define SEQ   512
#define BATCH 128
#define DIN   512
#define DH    1024
#define DOUT  256
#define WROW  (DIN + DH)   // 1536
#define MTOT  (SEQ * BATCH)  // 65536

#define NBLK   128
#define NTHR   256
#define KSPLIT 8
#define KSL    128
#define JT     64

// ---- SMEM layout for k_rnn (bytes) ----
#define SWF_OFF    0
#define SWF_BYTES  32768
#define SH_OFF     32768
#define SH_STRIDE  576
#define SMEM_RNN   (SWF_BYTES + BATCH * SH_STRIDE)   // 106496 B

// ---- SMEM layout for k_xw_mma ----
// double buffer x 4 arrays x [128 rows][20 u32] (16 data u32 + 4 pad)
#define XA_BYTES   10240                    // one array, one buffer
#define XBUF_BYTES (4 * XA_BYTES)           // 40960
#define SMEM_XW    (2 * XBUF_BYTES)         // 81920

// Device-global scratch
__device__ float         g_xW[SEQ * BATCH * DH];
__device__ float         g_H[BATCH * DH];
__device__ uint32_t      g_H2[BATCH * 1024];
__device__ float         g_Cpart[KSPLIT * BATCH * DH];
__device__ __nv_bfloat16 g_Ahi[MTOT * DIN];   // x hi, [65536][512]
__device__ __nv_bfloat16 g_Alo[MTOT * DIN];
__device__ __nv_bfloat16 g_Bhi[DH * DIN];     // Wx hi, [1024 n][512 k]
__device__ __nv_bfloat16 g_Blo[DH * DIN];
__device__ unsigned      g_bar_count;
__device__ unsigned      g_bar_flag;

// ---------------- helpers ----------------
__device__ __forceinline__ uint32_t bf16pair(float lo_elem, float hi_elem) {
    __nv_bfloat162 p = __floats2bfloat162_rn(lo_elem, hi_elem);
    return *(uint32_t*)&p;
}
__device__ __forceinline__ float bf16of(float x) {
    return __bfloat162float(__float2bfloat16(x));
}
__device__ __forceinline__ void mma16(float* d,
                                      uint32_t a0, uint32_t a1, uint32_t a2, uint32_t a3,
                                      uint32_t b0, uint32_t b1) {
    asm volatile(
        "mma.sync.aligned.m16n8k16.row.col.f32.bf16.bf16.f32 "
        "{%0,%1,%2,%3}, {%4,%5,%6,%7}, {%8,%9}, {%0,%1,%2,%3};"
        : "+f"(d[0]), "+f"(d[1]), "+f"(d[2]), "+f"(d[3])
        : "r"(a0), "r"(a1), "r"(a2), "r"(a3), "r"(b0), "r"(b1));
}
__device__ __forceinline__ void cpasync16(void* smem_dst, const void* gsrc) {
    uint32_t d = (uint32_t)__cvta_generic_to_shared(smem_dst);
    asm volatile("cp.async.cg.shared.global [%0], [%1], 16;"
                 :: "r"(d), "l"(gsrc) : "memory");
}

// ---------------------------------------------------------------------------
__global__ void k_init(const float* __restrict__ hidden)
{
    int i = blockIdx.x * blockDim.x + threadIdx.x;
    if (i < BATCH * DH) g_H[i] = hidden[i];
    if (i < BATCH * DH / 2) {
        int b = i >> 9;
        int k = (i & 511) << 1;
        float x0 = hidden[b * DH + k];
        float x1 = hidden[b * DH + k + 1];
        float h0 = bf16of(x0), h1 = bf16of(x1);
        int o = (k >> 4) * 16 + (((k & 7) >> 1) << 2) + (((k >> 3) & 1) << 1);
        g_H2[b * 1024 + o]     = bf16pair(h0, h1);
        g_H2[b * 1024 + o + 1] = bf16pair(x0 - h0, x1 - h1);
    }
    if (i == 0) { g_bar_count = 0; g_bar_flag = 0; }
}

// ---------------------------------------------------------------------------
// Split x and Wx into bf16 hi/lo arrays (k-contiguous, fragment-ready pairs).
// ---------------------------------------------------------------------------
__global__ void k_prep(const float* __restrict__ x, const float* __restrict__ W)
{
    long i = (long)blockIdx.x * blockDim.x + threadIdx.x;
    if (i < (long)MTOT * DIN) {
        float v = x[i];
        float h = bf16of(v);
        g_Ahi[i] = __float2bfloat16(h);
        g_Alo[i] = __float2bfloat16(v - h);
    } else {
        long j = i - (long)MTOT * DIN;
        if (j < (long)DH * DIN) {
            int n = (int)(j >> 9);
            int k = (int)(j & 511);
            float v = W[n * WROW + k];
            float h = bf16of(v);
            g_Bhi[j] = __float2bfloat16(h);
            g_Blo[j] = __float2bfloat16(v - h);
        }
    }
}

// ---------------------------------------------------------------------------
// xW = x @ Wx on tensor cores: bf16x3 m16n8k16, 128x128 block tile, BK=32,
// double-buffered cp.async. Warp grid 4m x 2n; per-warp 2 m-frags x 8 n-frags.
// ---------------------------------------------------------------------------
__global__ void __launch_bounds__(256) k_xw_mma()
{
    extern __shared__ char smem[];

    const int tid  = threadIdx.x;
    const int n0   = blockIdx.x << 7;
    const int m0   = blockIdx.y << 7;
    const int wrp  = tid >> 5;
    const int lane = tid & 31;
    const int g    = lane >> 2;
    const int tq   = lane & 3;
    const int wm   = wrp & 3;        // 4 m-warps, 32 rows each
    const int wn   = wrp >> 2;       // 2 n-warps, 64 cols each

    // smem u32 pointers per (buffer, array)
    auto sA_hi = [&](int b) { return (uint32_t*)(smem + b * XBUF_BYTES); };
    auto sA_lo = [&](int b) { return (uint32_t*)(smem + b * XBUF_BYTES + XA_BYTES); };
    auto sB_hi = [&](int b) { return (uint32_t*)(smem + b * XBUF_BYTES + 2 * XA_BYTES); };
    auto sB_lo = [&](int b) { return (uint32_t*)(smem + b * XBUF_BYTES + 3 * XA_BYTES); };

    // issue one BK=32 chunk into buffer b
    auto issue = [&](int cb, int b) {
        char* base = smem + b * XBUF_BYTES;
        #pragma unroll
        for (int it = 0; it < 8; ++it) {
            int p    = tid + it * 256;        // 0..2047
            int arr  = p >> 9;                // 0:Ahi 1:Alo 2:Bhi 3:Blo
            int rem  = p & 511;
            int row  = rem >> 2;
            int seg  = rem & 3;
            char* dst = base + arr * XA_BYTES + row * 80 + seg * 16;
            const __nv_bfloat16* src;
            if (arr == 0)      src = &g_Ahi[(long)(m0 + row) * DIN + cb * 32 + seg * 8];
            else if (arr == 1) src = &g_Alo[(long)(m0 + row) * DIN + cb * 32 + seg * 8];
            else if (arr == 2) src = &g_Bhi[(long)(n0 + row) * DIN + cb * 32 + seg * 8];
            else               src = &g_Blo[(long)(n0 + row) * DIN + cb * 32 + seg * 8];
            cpasync16(dst, src);
        }
        asm volatile("cp.async.commit_group;" ::: "memory");
    };

    float acc[2][8][4];
    #pragma unroll
    for (int mf = 0; mf < 2; ++mf)
        #pragma unroll
        for (int nf = 0; nf < 8; ++nf)
            #pragma unroll
            for (int c = 0; c < 4; ++c) acc[mf][nf][c] = 0.f;

    issue(0, 0);

    for (int cb = 0; cb < 16; ++cb) {
        const int buf = cb & 1;
        if (cb + 1 < 16) {
            issue(cb + 1, buf ^ 1);
            asm volatile("cp.async.wait_group 1;" ::: "memory");
        } else {
            asm volatile("cp.async.wait_group 0;" ::: "memory");
        }
        __syncthreads();

        const uint32_t* ah = sA_hi(buf);
        const uint32_t* al = sA_lo(buf);
        const uint32_t* bh = sB_hi(buf);
        const uint32_t* bl = sB_lo(buf);

        #pragma unroll
        for (int kc = 0; kc < 2; ++kc) {
            uint32_t AH[2][4], AL[2][4];
            #pragma unroll
            for (int mf = 0; mf < 2; ++mf) {
                int r0 = wm * 32 + mf * 16 + g;
                AH[mf][0] = ah[r0 * 20 + kc * 8 + tq];
                AH[mf][1] = ah[(r0 + 8) * 20 + kc * 8 + tq];
                AH[mf][2] = ah[r0 * 20 + kc * 8 + tq + 4];
                AH[mf][3] = ah[(r0 + 8) * 20 + kc * 8 + tq + 4];
                AL[mf][0] = al[r0 * 20 + kc * 8 + tq];
                AL[mf][1] = al[(r0 + 8) * 20 + kc * 8 + tq];
                AL[mf][2] = al[r0 * 20 + kc * 8 + tq + 4];
                AL[mf][3] = al[(r0 + 8) * 20 + kc * 8 + tq + 4];
            }
            #pragma unroll
            for (int nf = 0; nf < 8; ++nf) {
                int nr = wn * 64 + nf * 8 + g;
                uint32_t b0h = bh[nr * 20 + kc * 8 + tq];
                uint32_t b1h = bh[nr * 20 + kc * 8 + tq + 4];
                uint32_t b0l = bl[nr * 20 + kc * 8 + tq];
                uint32_t b1l = bl[nr * 20 + kc * 8 + tq + 4];
                #pragma unroll
                for (int mf = 0; mf < 2; ++mf) {
                    mma16(acc[mf][nf], AH[mf][0], AH[mf][1], AH[mf][2], AH[mf][3], b0h, b1h);
                    mma16(acc[mf][nf], AL[mf][0], AL[mf][1], AL[mf][2], AL[mf][3], b0h, b1h);
                    mma16(acc[mf][nf], AH[mf][0], AH[mf][1], AH[mf][2], AH[mf][3], b0l, b1l);
                }
            }
        }
        __syncthreads();
    }

    // epilogue: D[g][2t,2t+1] / D[g+8][...] per frag
    #pragma unroll
    for (int mf = 0; mf < 2; ++mf) {
        int r0 = m0 + wm * 32 + mf * 16 + g;
        #pragma unroll
        for (int nf = 0; nf < 8; ++nf) {
            int c = n0 + wn * 64 + nf * 8 + (tq << 1);
            *(float2*)&g_xW[(long)r0 * DH + c]       = make_float2(acc[mf][nf][0], acc[mf][nf][1]);
            *(float2*)&g_xW[(long)(r0 + 8) * DH + c] = make_float2(acc[mf][nf][2], acc[mf][nf][3]);
        }
    }
}

// ---------------------------------------------------------------------------
__device__ __forceinline__ void grid_barrier(unsigned nblk, unsigned& gen)
{
    __threadfence();
    __syncthreads();
    if (threadIdx.x == 0) {
        gen += 1;
        unsigned a = atomicAdd(&g_bar_count, 1u);
        if (a == nblk - 1u) {
            atomicExch(&g_bar_count, 0u);
            __threadfence();
            *(volatile unsigned*)&g_bar_flag = gen;
        } else {
            while (*(volatile unsigned*)&g_bar_flag != gen) { }
        }
    }
    __syncthreads();
}

// ---------------------------------------------------------------------------
// Persistent recurrence (unchanged from R11 WIN).
// ---------------------------------------------------------------------------
__global__ void __launch_bounds__(NTHR, 1) k_rnn(
    const float* __restrict__ Wi2h, const float* __restrict__ bi2h,
    const float* __restrict__ Wh2o, const float* __restrict__ bh2o,
    float* __restrict__ out, int out_size)
{
    extern __shared__ char smem[];
    const uint4* sWf = (const uint4*)(smem + SWF_OFF);

    const int tid  = threadIdx.x;
    const int blk  = blockIdx.x;
    const int jx   = blk & 15;
    const int kx   = blk >> 4;
    const int j0   = jx * JT;
    const int k0   = kx * KSL;
    const int wrp  = tid >> 5;
    const int lane = tid & 31;
    const int g    = lane >> 2;
    const int tq   = lane & 3;
    const int brow = (wrp << 4) + g;

    for (int p = tid; p < 8 * 8 * 32; p += NTHR) {
        int kc = p >> 8;
        int nt = (p >> 5) & 7;
        int ln = p & 31;
        int t  = ln & 3;
        int n  = j0 + nt * 8 + (ln >> 2);
        const float* wrow = &Wi2h[n * WROW + DIN + k0 + kc * 16];
        float w0 = wrow[2*t],     w1 = wrow[2*t + 1];
        float w2 = wrow[2*t + 8], w3 = wrow[2*t + 9];
        float h0 = bf16of(w0), h1 = bf16of(w1), h2 = bf16of(w2), h3 = bf16of(w3);
        uint4 frag;
        frag.x = bf16pair(h0, h1);
        frag.y = bf16pair(h2, h3);
        frag.z = bf16pair(w0 - h0, w1 - h1);
        frag.w = bf16pair(w2 - h2, w3 - h3);
        ((uint4*)(smem + SWF_OFF))[p] = frag;
    }

    unsigned gen = 0;
    const int gtid = blk * NTHR + tid;
    const float4* Cp4 = (const float4*)g_Cpart;
    const float4* xW4 = (const float4*)g_xW;
    float4* H4 = (float4*)g_H;
    const int pj = (gtid << 2) & (DH - 1);
    const float4 bias = *(const float4*)&bi2h[pj];

    float* part_row0 = &g_Cpart[kx * (BATCH * DH) + brow * DH + j0 + (tq << 1)];

    const int rem  = pj & 15;
    const int tqA  = (rem & 7) >> 1;
    const int half = (rem >> 3) & 1;
    uint32_t* h2row = &g_H2[(gtid >> 8) * 1024 + (pj >> 4) * 16 + tqA * 4 + half * 2];

    const char* h2src = (const char*)g_H2 + (size_t)kx * 512;

    for (int t = 0; t < SEQ; ++t) {
        for (int p = tid; p < BATCH * 32; p += NTHR) {
            int r   = p >> 5;
            int c16 = p & 31;
            uint32_t dst = (uint32_t)__cvta_generic_to_shared(
                smem + SH_OFF + r * SH_STRIDE + c16 * 16);
            const char* src = h2src + (size_t)r * 4096 + c16 * 16;
            asm volatile("cp.async.cg.shared.global [%0], [%1], 16;"
                         :: "r"(dst), "l"(src) : "memory");
        }
        asm volatile("cp.async.commit_group;" ::: "memory");
        asm volatile("cp.async.wait_group 0;" ::: "memory");
        __syncthreads();

        float acc[8][4];
        #pragma unroll
        for (int nt = 0; nt < 8; ++nt)
            #pragma unroll
            for (int c = 0; c < 4; ++c) acc[nt][c] = 0.f;

        #pragma unroll 2
        for (int kc = 0; kc < 8; ++kc) {
            uint4 U0 = *(const uint4*)(smem + SH_OFF + brow * SH_STRIDE + kc * 64 + tq * 16);
            uint4 U1 = *(const uint4*)(smem + SH_OFF + (brow + 8) * SH_STRIDE + kc * 64 + tq * 16);
            uint32_t ah0 = U0.x, al0 = U0.y, ah2 = U0.z, al2 = U0.w;
            uint32_t ah1 = U1.x, al1 = U1.y, ah3 = U1.z, al3 = U1.w;
            #pragma unroll
            for (int nt = 0; nt < 8; ++nt) {
                uint4 bf = sWf[((kc << 3) + nt) * 32 + lane];
                mma16(acc[nt], ah0, ah1, ah2, ah3, bf.x, bf.y);
                mma16(acc[nt], al0, al1, al2, al3, bf.x, bf.y);
                mma16(acc[nt], ah0, ah1, ah2, ah3, bf.z, bf.w);
            }
        }

        #pragma unroll
        for (int nt = 0; nt < 8; ++nt) {
            *(float2*)(part_row0 + nt * 8)          = make_float2(acc[nt][0], acc[nt][1]);
            *(float2*)(part_row0 + 8 * DH + nt * 8) = make_float2(acc[nt][2], acc[nt][3]);
        }

        grid_barrier(gridDim.x, gen);

        {
            float4 s = Cp4[gtid];
            #pragma unroll
            for (int sp = 1; sp < KSPLIT; ++sp) {
                float4 c = Cp4[sp * 32768 + gtid];
                s.x += c.x; s.y += c.y; s.z += c.z; s.w += c.w;
            }
            float4 xw = xW4[t * 32768 + gtid];
            float4 r;
            r.x = tanhf(s.x + xw.x + bias.x);
            r.y = tanhf(s.y + xw.y + bias.y);
            r.z = tanhf(s.z + xw.z + bias.z);
            r.w = tanhf(s.w + xw.w + bias.w);

            float hx = bf16of(r.x), hy = bf16of(r.y);
            float hz = bf16of(r.z), hw = bf16of(r.w);
            h2row[0] = bf16pair(hx, hy);
            h2row[1] = bf16pair(r.x - hx, r.y - hy);
            h2row[4] = bf16pair(hz, hw);
            h2row[5] = bf16pair(r.z - hz, r.w - hw);

            if (t == SEQ - 1) H4[gtid] = r;
        }

        grid_barrier(gridDim.x, gen);
    }

    // ------------------- Epilogue: logits + softmax -------------------
    {
        float* sv   = (float*)smem;
        float* sred = (float*)smem + 1024;
        const int b = blk;

        ((float4*)sv)[tid] = *(const float4*)&g_H[b * DH + (tid << 2)];
        __syncthreads();

        float acc = 0.f;
        const float4* wr = (const float4*)(Wh2o + tid * DH);
        #pragma unroll 8
        for (int qq = 0; qq < DH / 4; ++qq) {
            float4 w = wr[qq];
            float4 h = ((const float4*)sv)[qq];
            acc += w.x * h.x + w.y * h.y + w.z * h.z + w.w * h.w;
        }
        float logit = acc + bh2o[tid];

        sred[tid] = logit;
        __syncthreads();
        for (int s = 128; s > 0; s >>= 1) {
            if (tid < s) sred[tid] = fmaxf(sred[tid], sred[tid + s]);
            __syncthreads();
        }
        float mx = sred[0];
        __syncthreads();
        float e = expf(logit - mx);
        sred[tid] = e;
        __syncthreads();
        for (int s = 128; s > 0; s >>= 1) {
            if (tid < s) sred[tid] += sred[tid + s];
            __syncthreads();
        }
        float inv = 1.f / sred[0];
        out[b * DOUT + tid] = e * inv;
    }

    if (out_size >= BATCH * DOUT + BATCH * DH) {
        for (int i = gtid; i < BATCH * DH; i += NBLK * NTHR)
            out[BATCH * DOUT + i] = g_H[i];
    }
}

// ---------------------------------------------------------------------------
extern "C" void kernel_launch(void* const* d_in, const int* in_sizes, int n_in,
                              void* d_out, int out_size)
{
    const float* x      = (const float*)d_in[0];
    const float* hidden = (const float*)d_in[1];
    const float* Wi2h   = (const float*)d_in[2];
    const float* bi2h   = (const float*)d_in[3];
    const float* Wh2o   = (const float*)d_in[4];
    const float* bh2o   = (const float*)d_in[5];
    float* out = (float*)d_out;

    cudaFuncSetAttribute(k_rnn, cudaFuncAttributeMaxDynamicSharedMemorySize,
                         SMEM_RNN);
    cudaFuncSetAttribute(k_xw_mma, cudaFuncAttributeMaxDynamicSharedMemorySize,
                         SMEM_XW);

    k_init<<<512, 256>>>(hidden);

    long prep_items = (long)MTOT * DIN + (long)DH * DIN;   // 34,078,720
    k_prep<<<(int)((prep_items + 255) / 256), 256>>>(x, Wi2h);

    dim3 gx(DH / 128, MTOT / 128);   // (8, 512)
    k_xw_mma<<<gx, 256, SMEM_XW>>>();

    k_rnn<<<NBLK, NTHR, SMEM_RNN>>>(Wi2h, bi2h, Wh2o, bh2o, out, out_size);
}

// round 14
// speedup vs baseline: 1.9756x; 1.0563x over previous
#include <cuda_runtime.h>
#include <cuda_bf16.h>
#include <cstdint>

#define SEQ   512
#define BATCH 128
#define DIN   512
#define DH    1024
#define DOUT  256
#define WROW  (DIN + DH)   // 1536
#define MTOT  (SEQ * BATCH)  // 65536

#define NBLK   128
#define NTHR   512          // k_rnn: 16 warps
#define KSPLIT 8
#define KSL    128
#define JT     64

// ---- SMEM layout for k_rnn (bytes) ----
#define SWF_OFF    0
#define SWF_BYTES  32768
#define SH_OFF     32768
#define SH_STRIDE  576
#define SMEM_RNN   (SWF_BYTES + BATCH * SH_STRIDE)   // 106496 B

// ---- SMEM layout for k_xw_mma (fragment-ordered staging) ----
// per buffer: A[128 rows x 192B] + B[128 rows x 192B]; stride 192 = 64 mod 128
#define XROW_B     192
#define XARR_B     (128 * XROW_B)           // 24576
#define XBUF_B     (2 * XARR_B)             // 49152
#define SMEM_XW    (2 * XBUF_B)             // 98304

// Device-global scratch
__device__ float    g_xW[SEQ * BATCH * DH];     // fp32 input projections
__device__ float    g_H[BATCH * DH];            // fp32 H (final step)
__device__ uint32_t g_H2[BATCH * 1024];         // hi/lo bf16 pairs, frag-ordered
__device__ float    g_Cpart[KSPLIT * BATCH * DH];
__device__ uint32_t g_A2[(long)MTOT * 512];     // x hi/lo pairs, frag-ordered
__device__ uint32_t g_B2[DH * 512];             // Wx hi/lo pairs, frag-ordered
__device__ unsigned g_bar_count;
__device__ unsigned g_bar_flag;

// ---------------- helpers ----------------
__device__ __forceinline__ uint32_t bf16pair(float e0, float e1) {
    __nv_bfloat162 p = __floats2bfloat162_rn(e0, e1);
    return *(uint32_t*)&p;
}
__device__ __forceinline__ float bf16of(float x) {
    return __bfloat162float(__float2bfloat16(x));
}
__device__ __forceinline__ void mma16(float* d,
                                      uint32_t a0, uint32_t a1, uint32_t a2, uint32_t a3,
                                      uint32_t b0, uint32_t b1) {
    asm volatile(
        "mma.sync.aligned.m16n8k16.row.col.f32.bf16.bf16.f32 "
        "{%0,%1,%2,%3}, {%4,%5,%6,%7}, {%8,%9}, {%0,%1,%2,%3};"
        : "+f"(d[0]), "+f"(d[1]), "+f"(d[2]), "+f"(d[3])
        : "r"(a0), "r"(a1), "r"(a2), "r"(a3), "r"(b0), "r"(b1));
}
__device__ __forceinline__ void cpasync16(void* smem_dst, const void* gsrc) {
    uint32_t d = (uint32_t)__cvta_generic_to_shared(smem_dst);
    asm volatile("cp.async.cg.shared.global [%0], [%1], 16;"
                 :: "r"(d), "l"(gsrc) : "memory");
}
// frag-ordered u32 slot for even column j within a 512/1024-col row
__device__ __forceinline__ int frag_slot(int j) {
    return (j >> 4) * 16 + (((j & 7) >> 1) << 2) + (((j >> 3) & 1) << 1);
}

// ---------------------------------------------------------------------------
__global__ void k_init(const float* __restrict__ hidden)
{
    int i = blockIdx.x * blockDim.x + threadIdx.x;
    if (i < BATCH * DH) g_H[i] = hidden[i];
    if (i < BATCH * DH / 2) {
        int b = i >> 9;
        int j = (i & 511) << 1;
        float x0 = hidden[b * DH + j];
        float x1 = hidden[b * DH + j + 1];
        float h0 = bf16of(x0), h1 = bf16of(x1);
        int o = frag_slot(j);
        g_H2[b * 1024 + o]     = bf16pair(h0, h1);
        g_H2[b * 1024 + o + 1] = bf16pair(x0 - h0, x1 - h1);
    }
    if (i == 0) { g_bar_count = 0; g_bar_flag = 0; }
}

// ---------------------------------------------------------------------------
// Split x and Wx into fragment-ordered hi/lo bf16-pair arrays.
// ---------------------------------------------------------------------------
#define A_PAIRS ((long)MTOT * 256)
__global__ void k_prep(const float* __restrict__ x, const float* __restrict__ W)
{
    long i = (long)blockIdx.x * blockDim.x + threadIdx.x;
    if (i < A_PAIRS) {
        long m = i >> 8;
        int  j = (int)(i & 255) << 1;
        float v0 = x[m * 512 + j], v1 = x[m * 512 + j + 1];
        float h0 = bf16of(v0), h1 = bf16of(v1);
        int o = frag_slot(j);
        g_A2[m * 512 + o]     = bf16pair(h0, h1);
        g_A2[m * 512 + o + 1] = bf16pair(v0 - h0, v1 - h1);
    } else {
        long ib = i - A_PAIRS;
        if (ib < (long)DH * 256) {
            int n = (int)(ib >> 8);
            int j = (int)(ib & 255) << 1;
            float v0 = W[n * WROW + j], v1 = W[n * WROW + j + 1];
            float h0 = bf16of(v0), h1 = bf16of(v1);
            int o = frag_slot(j);
            g_B2[n * 512 + o]     = bf16pair(h0, h1);
            g_B2[n * 512 + o + 1] = bf16pair(v0 - h0, v1 - h1);
        }
    }
}

// ---------------------------------------------------------------------------
// xW = x @ Wx, bf16x3 m16n8k16, fragment-ordered staging, BK=32, dbl buffer.
// 256 threads: warp grid 4m x 2n; per-warp 2 m-frags x 8 n-frags.
// ---------------------------------------------------------------------------
__global__ void __launch_bounds__(256) k_xw_mma()
{
    extern __shared__ char smem[];

    const int tid  = threadIdx.x;
    const int n0   = blockIdx.x << 7;
    const int m0   = blockIdx.y << 7;
    const int wrp  = tid >> 5;
    const int lane = tid & 31;
    const int g    = lane >> 2;
    const int tq   = lane & 3;
    const int wm   = wrp & 3;
    const int wn   = wrp >> 2;

    auto issue = [&](int cb, int b) {
        char* base = smem + b * XBUF_B;
        #pragma unroll
        for (int it = 0; it < 8; ++it) {
            int p   = tid + it * 256;         // 0..2047
            int arr = p >> 10;                // 0:A 1:B
            int rem = p & 1023;
            int row = rem >> 3;
            int seg = rem & 7;
            char* dst = base + arr * XARR_B + row * XROW_B + seg * 16;
            const uint32_t* src = arr == 0
                ? &g_A2[(long)(m0 + row) * 512 + cb * 32 + seg * 4]
                : &g_B2[(long)(n0 + row) * 512 + cb * 32 + seg * 4];
            cpasync16(dst, src);
        }
        asm volatile("cp.async.commit_group;" ::: "memory");
    };

    float acc[2][8][4];
    #pragma unroll
    for (int mf = 0; mf < 2; ++mf)
        #pragma unroll
        for (int nf = 0; nf < 8; ++nf)
            #pragma unroll
            for (int c = 0; c < 4; ++c) acc[mf][nf][c] = 0.f;

    issue(0, 0);

    for (int cb = 0; cb < 16; ++cb) {
        const int buf = cb & 1;
        if (cb + 1 < 16) {
            issue(cb + 1, buf ^ 1);
            asm volatile("cp.async.wait_group 1;" ::: "memory");
        } else {
            asm volatile("cp.async.wait_group 0;" ::: "memory");
        }
        __syncthreads();

        const char* sA = smem + buf * XBUF_B;
        const char* sB = smem + buf * XBUF_B + XARR_B;

        #pragma unroll
        for (int kc = 0; kc < 2; ++kc) {
            uint4 U0[2], U1[2];
            #pragma unroll
            for (int mf = 0; mf < 2; ++mf) {
                int r0 = wm * 32 + mf * 16 + g;
                U0[mf] = *(const uint4*)(sA + r0 * XROW_B + kc * 64 + tq * 16);
                U1[mf] = *(const uint4*)(sA + (r0 + 8) * XROW_B + kc * 64 + tq * 16);
            }
            #pragma unroll
            for (int nf = 0; nf < 8; ++nf) {
                int nr = wn * 64 + nf * 8 + g;
                uint4 V = *(const uint4*)(sB + nr * XROW_B + kc * 64 + tq * 16);
                // V = (b0h, b0l, b1h, b1l); U = (ah_k, al_k, ah_k8, al_k8)
                #pragma unroll
                for (int mf = 0; mf < 2; ++mf) {
                    mma16(acc[mf][nf], U0[mf].x, U1[mf].x, U0[mf].z, U1[mf].z, V.x, V.z);
                    mma16(acc[mf][nf], U0[mf].y, U1[mf].y, U0[mf].w, U1[mf].w, V.x, V.z);
                    mma16(acc[mf][nf], U0[mf].x, U1[mf].x, U0[mf].z, U1[mf].z, V.y, V.w);
                }
            }
        }
        __syncthreads();
    }

    #pragma unroll
    for (int mf = 0; mf < 2; ++mf) {
        int r0 = m0 + wm * 32 + mf * 16 + g;
        #pragma unroll
        for (int nf = 0; nf < 8; ++nf) {
            int c = n0 + wn * 64 + nf * 8 + (tq << 1);
            *(float2*)&g_xW[(long)r0 * DH + c]       = make_float2(acc[mf][nf][0], acc[mf][nf][1]);
            *(float2*)&g_xW[(long)(r0 + 8) * DH + c] = make_float2(acc[mf][nf][2], acc[mf][nf][3]);
        }
    }
}

// ---------------------------------------------------------------------------
__device__ __forceinline__ void grid_barrier(unsigned nblk, unsigned& gen)
{
    __threadfence();
    __syncthreads();
    if (threadIdx.x == 0) {
        gen += 1;
        unsigned a = atomicAdd(&g_bar_count, 1u);
        if (a == nblk - 1u) {
            atomicExch(&g_bar_count, 0u);
            __threadfence();
            *(volatile unsigned*)&g_bar_flag = gen;
        } else {
            while (*(volatile unsigned*)&g_bar_flag != gen) { }
        }
    }
    __syncthreads();
}

// ---------------------------------------------------------------------------
// Persistent recurrence, 512 threads (16 warps = 4/SMSP for MMA ILP).
// Warp w: batch rows [(w&7)*16, +16), n-tiles [ (w>>3)*4, +4 ).
// Pipelined H copy (2 cp.async groups) + early xW prefetch.
// ---------------------------------------------------------------------------
__global__ void __launch_bounds__(NTHR, 1) k_rnn(
    const float* __restrict__ Wi2h, const float* __restrict__ bi2h,
    const float* __restrict__ Wh2o, const float* __restrict__ bh2o,
    float* __restrict__ out, int out_size)
{
    extern __shared__ char smem[];
    const uint4* sWf = (const uint4*)(smem + SWF_OFF);

    const int tid    = threadIdx.x;
    const int blk    = blockIdx.x;
    const int jx     = blk & 15;
    const int kx     = blk >> 4;
    const int j0     = jx * JT;
    const int k0     = kx * KSL;
    const int wrp    = tid >> 5;
    const int lane   = tid & 31;
    const int g      = lane >> 2;
    const int tq     = lane & 3;
    const int brow   = (wrp & 7) * 16 + g;
    const int nthalf = wrp >> 3;

    // ---- Build B fragments (Wh hi/lo bf16, m16n8k16 layout) ONCE ----
    for (int p = tid; p < 8 * 8 * 32; p += NTHR) {
        int kc = p >> 8;
        int nt = (p >> 5) & 7;
        int ln = p & 31;
        int t  = ln & 3;
        int n  = j0 + nt * 8 + (ln >> 2);
        const float* wrow = &Wi2h[n * WROW + DIN + k0 + kc * 16];
        float w0 = wrow[2*t],     w1 = wrow[2*t + 1];
        float w2 = wrow[2*t + 8], w3 = wrow[2*t + 9];
        float h0 = bf16of(w0), h1 = bf16of(w1), h2 = bf16of(w2), h3 = bf16of(w3);
        uint4 frag;
        frag.x = bf16pair(h0, h1);          // b0 hi
        frag.y = bf16pair(h2, h3);          // b1 hi
        frag.z = bf16pair(w0 - h0, w1 - h1);// b0 lo
        frag.w = bf16pair(w2 - h2, w3 - h3);// b1 lo
        ((uint4*)(smem + SWF_OFF))[p] = frag;
    }

    unsigned gen = 0;
    const int gtid = blk * NTHR + tid;                 // 0..65535
    const float2* Cp2 = (const float2*)g_Cpart;        // 8 slabs x 65536
    const float2* xW2 = (const float2*)g_xW;
    const int pj = (gtid << 1) & (DH - 1);             // even j owned
    const float2 bias = make_float2(bi2h[pj], bi2h[pj + 1]);

    float* part_row0 = &g_Cpart[kx * (BATCH * DH) + brow * DH + j0 +
                                nthalf * 32 + (tq << 1)];

    const int h2r = gtid >> 9;                         // row for phase-2 write
    uint32_t* h2w = &g_H2[h2r * 1024 + frag_slot(pj)];

    const char* h2src = (const char*)g_H2 + (size_t)kx * 512;

    for (int t = 0; t < SEQ; ++t) {
        // ---- issue H copy in two halves (kc 0-3, kc 4-7) ----
        #pragma unroll
        for (int half = 0; half < 2; ++half) {
            for (int p = tid; p < BATCH * 16; p += NTHR) {
                int r   = p >> 4;
                int c16 = (p & 15) + half * 16;
                uint32_t dst = (uint32_t)__cvta_generic_to_shared(
                    smem + SH_OFF + r * SH_STRIDE + c16 * 16);
                const char* src = h2src + (size_t)r * 4096 + c16 * 16;
                asm volatile("cp.async.cg.shared.global [%0], [%1], 16;"
                             :: "r"(dst), "l"(src) : "memory");
            }
            asm volatile("cp.async.commit_group;" ::: "memory");
        }

        // ---- prefetch xW (DRAM) while copies fly ----
        float2 xw_pre = __ldg(&xW2[(size_t)t * 65536 + gtid]);

        float acc[4][4];
        #pragma unroll
        for (int nt = 0; nt < 4; ++nt)
            #pragma unroll
            for (int c = 0; c < 4; ++c) acc[nt][c] = 0.f;

        // ---- first half arrived? MMA kc 0-3 ----
        asm volatile("cp.async.wait_group 1;" ::: "memory");
        __syncthreads();
        #pragma unroll
        for (int kc = 0; kc < 4; ++kc) {
            uint4 U0 = *(const uint4*)(smem + SH_OFF + brow * SH_STRIDE + kc * 64 + tq * 16);
            uint4 U1 = *(const uint4*)(smem + SH_OFF + (brow + 8) * SH_STRIDE + kc * 64 + tq * 16);
            #pragma unroll
            for (int np = 0; np < 4; ++np) {
                uint4 bf = sWf[((kc << 3) + nthalf * 4 + np) * 32 + lane];
                mma16(acc[np], U0.x, U1.x, U0.z, U1.z, bf.x, bf.y);
                mma16(acc[np], U0.y, U1.y, U0.w, U1.w, bf.x, bf.y);
                mma16(acc[np], U0.x, U1.x, U0.z, U1.z, bf.z, bf.w);
            }
        }
        // ---- second half ----
        asm volatile("cp.async.wait_group 0;" ::: "memory");
        __syncthreads();
        #pragma unroll
        for (int kc = 4; kc < 8; ++kc) {
            uint4 U0 = *(const uint4*)(smem + SH_OFF + brow * SH_STRIDE + kc * 64 + tq * 16);
            uint4 U1 = *(const uint4*)(smem + SH_OFF + (brow + 8) * SH_STRIDE + kc * 64 + tq * 16);
            #pragma unroll
            for (int np = 0; np < 4; ++np) {
                uint4 bf = sWf[((kc << 3) + nthalf * 4 + np) * 32 + lane];
                mma16(acc[np], U0.x, U1.x, U0.z, U1.z, bf.x, bf.y);
                mma16(acc[np], U0.y, U1.y, U0.w, U1.w, bf.x, bf.y);
                mma16(acc[np], U0.x, U1.x, U0.z, U1.z, bf.z, bf.w);
            }
        }

        #pragma unroll
        for (int np = 0; np < 4; ++np) {
            *(float2*)(part_row0 + np * 8)          = make_float2(acc[np][0], acc[np][1]);
            *(float2*)(part_row0 + 8 * DH + np * 8) = make_float2(acc[np][2], acc[np][3]);
        }

        grid_barrier(gridDim.x, gen);

        // ---- phase 2: reduce 8 partials + xW + bias, tanh -> g_H2 ----
        {
            float2 s = Cp2[gtid];
            #pragma unroll
            for (int sp = 1; sp < KSPLIT; ++sp) {
                float2 c = Cp2[sp * 65536 + gtid];
                s.x += c.x; s.y += c.y;
            }
            float rx = tanhf(s.x + xw_pre.x + bias.x);
            float ry = tanhf(s.y + xw_pre.y + bias.y);

            float hx = bf16of(rx), hy = bf16of(ry);
            h2w[0] = bf16pair(hx, hy);
            h2w[1] = bf16pair(rx - hx, ry - hy);

            if (t == SEQ - 1) ((float2*)g_H)[gtid] = make_float2(rx, ry);
        }

        grid_barrier(gridDim.x, gen);
    }

    // ------------------- Epilogue: logits + softmax -------------------
    {
        float* sv   = (float*)smem;          // h row [1024]
        float* sred = (float*)smem + 1024;   // reduction [256]
        const int b = blk;

        if (tid < 256)
            ((float4*)sv)[tid] = *(const float4*)&g_H[b * DH + (tid << 2)];
        __syncthreads();

        float logit = 0.f, e = 0.f;
        if (tid < 256) {
            float acc = 0.f;
            const float4* wr = (const float4*)(Wh2o + tid * DH);
            #pragma unroll 8
            for (int qq = 0; qq < DH / 4; ++qq) {
                float4 w = wr[qq];
                float4 h = ((const float4*)sv)[qq];
                acc += w.x * h.x + w.y * h.y + w.z * h.z + w.w * h.w;
            }
            logit = acc + bh2o[tid];
            sred[tid] = logit;
        }
        __syncthreads();
        for (int s = 128; s > 0; s >>= 1) {
            if (tid < s) sred[tid] = fmaxf(sred[tid], sred[tid + s]);
            __syncthreads();
        }
        float mx = sred[0];
        __syncthreads();
        if (tid < 256) {
            e = expf(logit - mx);
            sred[tid] = e;
        }
        __syncthreads();
        for (int s = 128; s > 0; s >>= 1) {
            if (tid < s) sred[tid] += sred[tid + s];
            __syncthreads();
        }
        if (tid < 256) {
            float inv = 1.f / sred[0];
            out[b * DOUT + tid] = e * inv;
        }
    }

    // h_final (second output tensor)
    if (out_size >= BATCH * DOUT + BATCH * DH) {
        for (int i = gtid; i < BATCH * DH; i += NBLK * NTHR)
            out[BATCH * DOUT + i] = g_H[i];
    }
}

// ---------------------------------------------------------------------------
extern "C" void kernel_launch(void* const* d_in, const int* in_sizes, int n_in,
                              void* d_out, int out_size)
{
    const float* x      = (const float*)d_in[0];
    const float* hidden = (const float*)d_in[1];
    const float* Wi2h   = (const float*)d_in[2];
    const float* bi2h   = (const float*)d_in[3];
    const float* Wh2o   = (const float*)d_in[4];
    const float* bh2o   = (const float*)d_in[5];
    float* out = (float*)d_out;

    cudaFuncSetAttribute(k_rnn, cudaFuncAttributeMaxDynamicSharedMemorySize,
                         SMEM_RNN);
    cudaFuncSetAttribute(k_xw_mma, cudaFuncAttributeMaxDynamicSharedMemorySize,
                         SMEM_XW);

    k_init<<<512, 256>>>(hidden);

    long prep_items = A_PAIRS + (long)DH * 256;
    k_prep<<<(int)((prep_items + 255) / 256), 256>>>(x, Wi2h);

    dim3 gx(DH / 128, MTOT / 128);   // (8, 512)
    k_xw_mma<<<gx, 256, SMEM_XW>>>();

    k_rnn<<<NBLK, NTHR, SMEM_RNN>>>(Wi2h, bi2h, Wh2o, bh2o, out, out_size);
}

// round 15
// speedup vs baseline: 2.0670x; 1.0463x over previous
#include <cuda_runtime.h>
#include <cuda_bf16.h>
#include <cstdint>

#define SEQ   512
#define BATCH 128
#define DIN   512
#define DH    1024
#define DOUT  256
#define WROW  (DIN + DH)   // 1536
#define MTOT  (SEQ * BATCH)  // 65536

#define NBLK   128
#define NTHR   512          // k_rnn: 16 warps
#define KSPLIT 8
#define KSL    128
#define JT     64

// ---- SMEM layout for k_rnn (bytes) ----
#define SWF_OFF    0
#define SWF_BYTES  32768
#define SH_OFF     32768
#define SH_STRIDE  576
#define SMEM_RNN   (SWF_BYTES + BATCH * SH_STRIDE)   // 106496 B

// ---- SMEM layout for k_xw_mma (3-stage, fragment-ordered staging) ----
#define XROW_B     192
#define XARR_B     (128 * XROW_B)           // 24576
#define XBUF_B     (2 * XARR_B)             // 49152
#define SMEM_XW    (3 * XBUF_B)             // 147456

// Device-global scratch
__device__ float    g_xW[SEQ * BATCH * DH];
__device__ float    g_H[BATCH * DH];
__device__ uint32_t g_H2[BATCH * 1024];
__device__ float    g_Cpart[KSPLIT * BATCH * DH];
__device__ uint32_t g_A2[(long)MTOT * 512];
__device__ uint32_t g_B2[DH * 512];
__device__ unsigned g_bar_count;
__device__ unsigned g_bar_flag;

// ---------------- helpers ----------------
__device__ __forceinline__ uint32_t bf16pair(float e0, float e1) {
    __nv_bfloat162 p = __floats2bfloat162_rn(e0, e1);
    return *(uint32_t*)&p;
}
__device__ __forceinline__ float bf16of(float x) {
    return __bfloat162float(__float2bfloat16(x));
}
__device__ __forceinline__ void mma16(float* d,
                                      uint32_t a0, uint32_t a1, uint32_t a2, uint32_t a3,
                                      uint32_t b0, uint32_t b1) {
    asm volatile(
        "mma.sync.aligned.m16n8k16.row.col.f32.bf16.bf16.f32 "
        "{%0,%1,%2,%3}, {%4,%5,%6,%7}, {%8,%9}, {%0,%1,%2,%3};"
        : "+f"(d[0]), "+f"(d[1]), "+f"(d[2]), "+f"(d[3])
        : "r"(a0), "r"(a1), "r"(a2), "r"(a3), "r"(b0), "r"(b1));
}
__device__ __forceinline__ void cpasync16(void* smem_dst, const void* gsrc) {
    uint32_t d = (uint32_t)__cvta_generic_to_shared(smem_dst);
    asm volatile("cp.async.cg.shared.global [%0], [%1], 16;"
                 :: "r"(d), "l"(gsrc) : "memory");
}
__device__ __forceinline__ int frag_slot(int j) {
    return (j >> 4) * 16 + (((j & 7) >> 1) << 2) + (((j >> 3) & 1) << 1);
}

// ---------------------------------------------------------------------------
__global__ void k_init(const float* __restrict__ hidden)
{
    int i = blockIdx.x * blockDim.x + threadIdx.x;
    if (i < BATCH * DH) g_H[i] = hidden[i];
    if (i < BATCH * DH / 2) {
        int b = i >> 9;
        int j = (i & 511) << 1;
        float x0 = hidden[b * DH + j];
        float x1 = hidden[b * DH + j + 1];
        float h0 = bf16of(x0), h1 = bf16of(x1);
        int o = frag_slot(j);
        g_H2[b * 1024 + o]     = bf16pair(h0, h1);
        g_H2[b * 1024 + o + 1] = bf16pair(x0 - h0, x1 - h1);
    }
    if (i == 0) { g_bar_count = 0; g_bar_flag = 0; }
}

// ---------------------------------------------------------------------------
#define A_PAIRS ((long)MTOT * 256)
__global__ void k_prep(const float* __restrict__ x, const float* __restrict__ W)
{
    long i = (long)blockIdx.x * blockDim.x + threadIdx.x;
    if (i < A_PAIRS) {
        long m = i >> 8;
        int  j = (int)(i & 255) << 1;
        float v0 = x[m * 512 + j], v1 = x[m * 512 + j + 1];
        float h0 = bf16of(v0), h1 = bf16of(v1);
        int o = frag_slot(j);
        g_A2[m * 512 + o]     = bf16pair(h0, h1);
        g_A2[m * 512 + o + 1] = bf16pair(v0 - h0, v1 - h1);
    } else {
        long ib = i - A_PAIRS;
        if (ib < (long)DH * 256) {
            int n = (int)(ib >> 8);
            int j = (int)(ib & 255) << 1;
            float v0 = W[n * WROW + j], v1 = W[n * WROW + j + 1];
            float h0 = bf16of(v0), h1 = bf16of(v1);
            int o = frag_slot(j);
            g_B2[n * 512 + o]     = bf16pair(h0, h1);
            g_B2[n * 512 + o + 1] = bf16pair(v0 - h0, v1 - h1);
        }
    }
}

// ---------------------------------------------------------------------------
// xW = x @ Wx, bf16x3 m16n8k16, 3-stage cp.async pipeline, ONE sync per iter.
// ---------------------------------------------------------------------------
__global__ void __launch_bounds__(256) k_xw_mma()
{
    extern __shared__ char smem[];

    const int tid  = threadIdx.x;
    const int n0   = blockIdx.x << 7;
    const int m0   = blockIdx.y << 7;
    const int wrp  = tid >> 5;
    const int lane = tid & 31;
    const int g    = lane >> 2;
    const int tq   = lane & 3;
    const int wm   = wrp & 3;
    const int wn   = wrp >> 2;

    auto issue = [&](int cb) {
        char* base = smem + (cb % 3) * XBUF_B;
        #pragma unroll
        for (int it = 0; it < 8; ++it) {
            int p   = tid + it * 256;
            int arr = p >> 10;
            int rem = p & 1023;
            int row = rem >> 3;
            int seg = rem & 7;
            char* dst = base + arr * XARR_B + row * XROW_B + seg * 16;
            const uint32_t* src = arr == 0
                ? &g_A2[(long)(m0 + row) * 512 + cb * 32 + seg * 4]
                : &g_B2[(long)(n0 + row) * 512 + cb * 32 + seg * 4];
            cpasync16(dst, src);
        }
        asm volatile("cp.async.commit_group;" ::: "memory");
    };

    float acc[2][8][4];
    #pragma unroll
    for (int mf = 0; mf < 2; ++mf)
        #pragma unroll
        for (int nf = 0; nf < 8; ++nf)
            #pragma unroll
            for (int c = 0; c < 4; ++c) acc[mf][nf][c] = 0.f;

    issue(0);
    issue(1);

    for (int cb = 0; cb < 16; ++cb) {
        asm volatile("cp.async.wait_group 1;" ::: "memory");   // cb's data in
        __syncthreads();   // visibility + everyone done reading buf (cb-1)%3... (cb+2)%3
        if (cb + 2 < 16) issue(cb + 2);

        const char* sA = smem + (cb % 3) * XBUF_B;
        const char* sB = sA + XARR_B;

        #pragma unroll
        for (int kc = 0; kc < 2; ++kc) {
            uint4 U0[2], U1[2];
            #pragma unroll
            for (int mf = 0; mf < 2; ++mf) {
                int r0 = wm * 32 + mf * 16 + g;
                U0[mf] = *(const uint4*)(sA + r0 * XROW_B + kc * 64 + tq * 16);
                U1[mf] = *(const uint4*)(sA + (r0 + 8) * XROW_B + kc * 64 + tq * 16);
            }
            #pragma unroll
            for (int nf = 0; nf < 8; ++nf) {
                int nr = wn * 64 + nf * 8 + g;
                uint4 V = *(const uint4*)(sB + nr * XROW_B + kc * 64 + tq * 16);
                #pragma unroll
                for (int mf = 0; mf < 2; ++mf) {
                    mma16(acc[mf][nf], U0[mf].x, U1[mf].x, U0[mf].z, U1[mf].z, V.x, V.z);
                    mma16(acc[mf][nf], U0[mf].y, U1[mf].y, U0[mf].w, U1[mf].w, V.x, V.z);
                    mma16(acc[mf][nf], U0[mf].x, U1[mf].x, U0[mf].z, U1[mf].z, V.y, V.w);
                }
            }
        }
    }

    #pragma unroll
    for (int mf = 0; mf < 2; ++mf) {
        int r0 = m0 + wm * 32 + mf * 16 + g;
        #pragma unroll
        for (int nf = 0; nf < 8; ++nf) {
            int c = n0 + wn * 64 + nf * 8 + (tq << 1);
            *(float2*)&g_xW[(long)r0 * DH + c]       = make_float2(acc[mf][nf][0], acc[mf][nf][1]);
            *(float2*)&g_xW[(long)(r0 + 8) * DH + c] = make_float2(acc[mf][nf][2], acc[mf][nf][3]);
        }
    }
}

// ---------------------------------------------------------------------------
// Grid barrier with acq_rel atomics — no MEMBAR.ALL.GPU.
// ---------------------------------------------------------------------------
__device__ __forceinline__ void grid_barrier(unsigned nblk, unsigned& gen)
{
    __syncthreads();
    if (threadIdx.x == 0) {
        gen += 1;
        unsigned a;
        asm volatile("atom.acq_rel.gpu.global.add.u32 %0, [%1], 1;"
                     : "=r"(a) : "l"(&g_bar_count) : "memory");
        if (a == nblk - 1u) {
            asm volatile("st.relaxed.gpu.global.u32 [%0], %1;"
                         :: "l"(&g_bar_count), "r"(0u) : "memory");
            asm volatile("st.release.gpu.global.u32 [%0], %1;"
                         :: "l"(&g_bar_flag), "r"(gen) : "memory");
        } else {
            unsigned f;
            do {
                asm volatile("ld.acquire.gpu.global.u32 %0, [%1];"
                             : "=r"(f) : "l"(&g_bar_flag) : "memory");
            } while (f != gen);
        }
    }
    __syncthreads();
}

// ---------------------------------------------------------------------------
// Persistent recurrence: 512 threads, 4-chunk pipelined H copy, acq/rel
// barriers. Warp w: batch rows [(w&7)*16,+16), n-tiles [(w>>3)*4,+4).
// ---------------------------------------------------------------------------
__global__ void __launch_bounds__(NTHR, 1) k_rnn(
    const float* __restrict__ Wi2h, const float* __restrict__ bi2h,
    const float* __restrict__ Wh2o, const float* __restrict__ bh2o,
    float* __restrict__ out, int out_size)
{
    extern __shared__ char smem[];
    const uint4* sWf = (const uint4*)(smem + SWF_OFF);

    const int tid    = threadIdx.x;
    const int blk    = blockIdx.x;
    const int jx     = blk & 15;
    const int kx     = blk >> 4;
    const int j0     = jx * JT;
    const int k0     = kx * KSL;
    const int wrp    = tid >> 5;
    const int lane   = tid & 31;
    const int g      = lane >> 2;
    const int tq     = lane & 3;
    const int brow   = (wrp & 7) * 16 + g;
    const int nthalf = wrp >> 3;

    for (int p = tid; p < 8 * 8 * 32; p += NTHR) {
        int kc = p >> 8;
        int nt = (p >> 5) & 7;
        int ln = p & 31;
        int t  = ln & 3;
        int n  = j0 + nt * 8 + (ln >> 2);
        const float* wrow = &Wi2h[n * WROW + DIN + k0 + kc * 16];
        float w0 = wrow[2*t],     w1 = wrow[2*t + 1];
        float w2 = wrow[2*t + 8], w3 = wrow[2*t + 9];
        float h0 = bf16of(w0), h1 = bf16of(w1), h2 = bf16of(w2), h3 = bf16of(w3);
        uint4 frag;
        frag.x = bf16pair(h0, h1);
        frag.y = bf16pair(h2, h3);
        frag.z = bf16pair(w0 - h0, w1 - h1);
        frag.w = bf16pair(w2 - h2, w3 - h3);
        ((uint4*)(smem + SWF_OFF))[p] = frag;
    }

    unsigned gen = 0;
    const int gtid = blk * NTHR + tid;
    const float2* Cp2 = (const float2*)g_Cpart;
    const float2* xW2 = (const float2*)g_xW;
    const int pj = (gtid << 1) & (DH - 1);
    const float2 bias = make_float2(bi2h[pj], bi2h[pj + 1]);

    float* part_row0 = &g_Cpart[kx * (BATCH * DH) + brow * DH + j0 +
                                nthalf * 32 + (tq << 1)];

    const int h2r = gtid >> 9;
    uint32_t* h2w = &g_H2[h2r * 1024 + frag_slot(pj)];

    const char* h2src = (const char*)g_H2 + (size_t)kx * 512;

    for (int t = 0; t < SEQ; ++t) {
        // ---- issue H copy as 4 chunks of 16 KB (kc pairs) ----
        #pragma unroll
        for (int q = 0; q < 4; ++q) {
            #pragma unroll
            for (int it = 0; it < 2; ++it) {
                int p   = tid + it * NTHR;         // 0..1023
                int r   = p >> 3;
                int c16 = (p & 7) + q * 8;
                uint32_t dst = (uint32_t)__cvta_generic_to_shared(
                    smem + SH_OFF + r * SH_STRIDE + c16 * 16);
                const char* src = h2src + (size_t)r * 4096 + c16 * 16;
                asm volatile("cp.async.cg.shared.global [%0], [%1], 16;"
                             :: "r"(dst), "l"(src) : "memory");
            }
            asm volatile("cp.async.commit_group;" ::: "memory");
        }

        // prefetch xW (DRAM) while copies fly
        float2 xw_pre = __ldg(&xW2[(size_t)t * 65536 + gtid]);

        float acc[4][4];
        #pragma unroll
        for (int nt = 0; nt < 4; ++nt)
            #pragma unroll
            for (int c = 0; c < 4; ++c) acc[nt][c] = 0.f;

        // ---- MMA interleaved with chunk arrivals ----
        #pragma unroll
        for (int q = 0; q < 4; ++q) {
            if (q == 0)      asm volatile("cp.async.wait_group 3;" ::: "memory");
            else if (q == 1) asm volatile("cp.async.wait_group 2;" ::: "memory");
            else if (q == 2) asm volatile("cp.async.wait_group 1;" ::: "memory");
            else             asm volatile("cp.async.wait_group 0;" ::: "memory");
            __syncthreads();
            #pragma unroll
            for (int kk = 0; kk < 2; ++kk) {
                int kc = q * 2 + kk;
                uint4 U0 = *(const uint4*)(smem + SH_OFF + brow * SH_STRIDE + kc * 64 + tq * 16);
                uint4 U1 = *(const uint4*)(smem + SH_OFF + (brow + 8) * SH_STRIDE + kc * 64 + tq * 16);
                #pragma unroll
                for (int np = 0; np < 4; ++np) {
                    uint4 bf = sWf[((kc << 3) + nthalf * 4 + np) * 32 + lane];
                    mma16(acc[np], U0.x, U1.x, U0.z, U1.z, bf.x, bf.y);
                    mma16(acc[np], U0.y, U1.y, U0.w, U1.w, bf.x, bf.y);
                    mma16(acc[np], U0.x, U1.x, U0.z, U1.z, bf.z, bf.w);
                }
            }
        }

        #pragma unroll
        for (int np = 0; np < 4; ++np) {
            *(float2*)(part_row0 + np * 8)          = make_float2(acc[np][0], acc[np][1]);
            *(float2*)(part_row0 + 8 * DH + np * 8) = make_float2(acc[np][2], acc[np][3]);
        }

        grid_barrier(gridDim.x, gen);

        // ---- phase 2: reduce 8 partials + xW + bias, tanh -> g_H2 ----
        {
            float2 s = Cp2[gtid];
            #pragma unroll
            for (int sp = 1; sp < KSPLIT; ++sp) {
                float2 c = Cp2[sp * 65536 + gtid];
                s.x += c.x; s.y += c.y;
            }
            float rx = tanhf(s.x + xw_pre.x + bias.x);
            float ry = tanhf(s.y + xw_pre.y + bias.y);

            float hx = bf16of(rx), hy = bf16of(ry);
            h2w[0] = bf16pair(hx, hy);
            h2w[1] = bf16pair(rx - hx, ry - hy);

            if (t == SEQ - 1) ((float2*)g_H)[gtid] = make_float2(rx, ry);
        }

        grid_barrier(gridDim.x, gen);
    }

    // ------------------- Epilogue: logits + softmax -------------------
    {
        float* sv   = (float*)smem;
        float* sred = (float*)smem + 1024;
        const int b = blk;

        if (tid < 256)
            ((float4*)sv)[tid] = *(const float4*)&g_H[b * DH + (tid << 2)];
        __syncthreads();

        float logit = 0.f, e = 0.f;
        if (tid < 256) {
            float acc = 0.f;
            const float4* wr = (const float4*)(Wh2o + tid * DH);
            #pragma unroll 8
            for (int qq = 0; qq < DH / 4; ++qq) {
                float4 w = wr[qq];
                float4 h = ((const float4*)sv)[qq];
                acc += w.x * h.x + w.y * h.y + w.z * h.z + w.w * h.w;
            }
            logit = acc + bh2o[tid];
            sred[tid] = logit;
        }
        __syncthreads();
        for (int s = 128; s > 0; s >>= 1) {
            if (tid < s) sred[tid] = fmaxf(sred[tid], sred[tid + s]);
            __syncthreads();
        }
        float mx = sred[0];
        __syncthreads();
        if (tid < 256) {
            e = expf(logit - mx);
            sred[tid] = e;
        }
        __syncthreads();
        for (int s = 128; s > 0; s >>= 1) {
            if (tid < s) sred[tid] += sred[tid + s];
            __syncthreads();
        }
        if (tid < 256) {
            float inv = 1.f / sred[0];
            out[b * DOUT + tid] = e * inv;
        }
    }

    if (out_size >= BATCH * DOUT + BATCH * DH) {
        for (int i = gtid; i < BATCH * DH; i += NBLK * NTHR)
            out[BATCH * DOUT + i] = g_H[i];
    }
}

// ---------------------------------------------------------------------------
extern "C" void kernel_launch(void* const* d_in, const int* in_sizes, int n_in,
                              void* d_out, int out_size)
{
    const float* x      = (const float*)d_in[0];
    const float* hidden = (const float*)d_in[1];
    const float* Wi2h   = (const float*)d_in[2];
    const float* bi2h   = (const float*)d_in[3];
    const float* Wh2o   = (const float*)d_in[4];
    const float* bh2o   = (const float*)d_in[5];
    float* out = (float*)d_out;

    cudaFuncSetAttribute(k_rnn, cudaFuncAttributeMaxDynamicSharedMemorySize,
                         SMEM_RNN);
    cudaFuncSetAttribute(k_xw_mma, cudaFuncAttributeMaxDynamicSharedMemorySize,
                         SMEM_XW);

    k_init<<<512, 256>>>(hidden);

    long prep_items = A_PAIRS + (long)DH * 256;
    k_prep<<<(int)((prep_items + 255) / 256), 256>>>(x, Wi2h);

    dim3 gx(DH / 128, MTOT / 128);   // (8, 512)
    k_xw_mma<<<gx, 256, SMEM_XW>>>();

    k_rnn<<<NBLK, NTHR, SMEM_RNN>>>(Wi2h, bi2h, Wh2o, bh2o, out, out_size);
}